// round 10
// baseline (speedup 1.0000x reference)
#include <cuda_runtime.h>
#include <cuda_bf16.h>
#include <math.h>
#include <stdint.h>

// ---------------------------------------------------------------------------
// Problem constants
// ---------------------------------------------------------------------------
#define BATCH 4
#define SEQ   4096
#define DIM   1024
#define HEADS 8
#define DH    64
#define WS    128
#define NWIN  32
#define INNER 512
#define JLEN  384
#define M_ROWS (BATCH * SEQ)   // 16384

#define NEG_INF (-3.402823466e+38f)

// ---------------------------------------------------------------------------
// Scratch (device globals; kernel_launch makes NO runtime API calls)
// g_xn / g_attn / g_wq / g_wo hold tf32-rounded, k-permuted data:
//   within each 32-k tile, element k lives at slot (k&3)*8 + (k>>2).
// ---------------------------------------------------------------------------
__device__ float g_xn  [M_ROWS * DIM];
__device__ float g_qkv [M_ROWS * DIM];      // normal layout (attn reads it)
__device__ float g_attn[M_ROWS * INNER];
__device__ float g_wq  [DIM * DIM];
__device__ float g_wo  [DIM * INNER];
__device__ float g_kcos[JLEN * DH];
__device__ float g_ksin[JLEN * DH];
__device__ float g_qcs [WS * DH];
__device__ float g_qsn [WS * DH];

// ---------------------------------------------------------------------------
// Helpers
// ---------------------------------------------------------------------------
__device__ __forceinline__ float f2tf32(float x) {
    uint32_t y;
    asm("cvt.rna.tf32.f32 %0, %1;" : "=r"(y) : "f"(x));
    return __uint_as_float(y);
}

__device__ __forceinline__ void mma_tf32(float* d,
                                         float a0, float a1,
                                         float a2, float a3,
                                         float b0, float b1) {
    asm volatile(
        "mma.sync.aligned.m16n8k8.row.col.f32.tf32.tf32.f32 "
        "{%0,%1,%2,%3}, {%4,%5,%6,%7}, {%8,%9}, {%0,%1,%2,%3};\n"
        : "+f"(d[0]), "+f"(d[1]), "+f"(d[2]), "+f"(d[3])
        : "r"(__float_as_uint(a0)), "r"(__float_as_uint(a1)),
          "r"(__float_as_uint(a2)), "r"(__float_as_uint(a3)),
          "r"(__float_as_uint(b0)), "r"(__float_as_uint(b1)));
}

__device__ __forceinline__ uint32_t cvta_smem(const void* p) {
    uint32_t a;
    asm("{ .reg .u64 t; cvta.to.shared.u64 t, %1; cvt.u32.u64 %0, t; }"
        : "=r"(a) : "l"(p));
    return a;
}

#define PERM(j) (((j) & 3) * 8 + ((j) >> 2))
// global k-permuted slot within a row (tile-local PERM, tile-preserving)
#define GSLOT(k) ((((k) >> 5) << 5) + (((k) & 3) << 3) + (((k) >> 2) & 7))

// ---------------------------------------------------------------------------
// Rotary / xpos coefficient precompute
// ---------------------------------------------------------------------------
__global__ void rope_precompute_kernel() {
    int idx = blockIdx.x * blockDim.x + threadIdx.x;
    if (idx >= JLEN * DH) return;
    int t = idx / DH;
    int e = idx % DH;
    int f = e & 31;
    float invf = powf(10000.0f, -(2.0f * (float)f) / (float)DH);
    float ang  = (float)t * invf;
    float sb   = (2.0f * (float)f + 0.4f * (float)DH) / (1.4f * (float)DH);
    float pw   = ((float)t - (float)(JLEN / 2)) / (float)(WS / 2);
    float sc   = powf(sb, pw);
    float c = cosf(ang), s = sinf(ang);
    g_kcos[idx] = c / sc;
    g_ksin[idx] = s / sc;
    if (t >= JLEN - WS) {
        int i = t - (JLEN - WS);
        g_qcs[i * DH + e] = c * sc * 0.125f;
        g_qsn[i * DH + e] = s * sc * 0.125f;
    }
}

// ---------------------------------------------------------------------------
// Weight pre-permute + tf32 round (one-off, ~1.5M elems)
// ---------------------------------------------------------------------------
__global__ void wperm_kernel(const float* __restrict__ w_qkv,
                             const float* __restrict__ w_out) {
    int idx = blockIdx.x * blockDim.x + threadIdx.x;
    if (idx < DIM * DIM) {
        int row = idx >> 10, k = idx & 1023;
        g_wq[(size_t)row * DIM + GSLOT(k)] = f2tf32(w_qkv[idx]);
    }
    if (idx < DIM * INNER) {
        int row = idx / INNER, k = idx % INNER;
        g_wo[(size_t)row * INNER + GSLOT(k)] = f2tf32(w_out[idx]);
    }
}

// ---------------------------------------------------------------------------
// LayerNorm -> g_xn (tf32-rounded, k-permuted)
// ---------------------------------------------------------------------------
__global__ void __launch_bounds__(256) ln_kernel(const float* __restrict__ x,
                                                 const float* __restrict__ gam,
                                                 const float* __restrict__ bet) {
    __shared__ float red [8];
    __shared__ float red2[8];
    __shared__ float s_mu, s_rstd;
    int row = blockIdx.x;
    int t = threadIdx.x;
    float4 v = ((const float4*)(x + (size_t)row * DIM))[t];
    float s  = v.x + v.y + v.z + v.w;
    float sq = v.x * v.x + v.y * v.y + v.z * v.z + v.w * v.w;
    #pragma unroll
    for (int o = 16; o > 0; o >>= 1) {
        s  += __shfl_xor_sync(0xffffffffu, s,  o);
        sq += __shfl_xor_sync(0xffffffffu, sq, o);
    }
    if ((t & 31) == 0) { red[t >> 5] = s; red2[t >> 5] = sq; }
    __syncthreads();
    if (t < 32) {
        float ss = (t < 8) ? red [t] : 0.0f;
        float qq = (t < 8) ? red2[t] : 0.0f;
        #pragma unroll
        for (int o = 4; o > 0; o >>= 1) {
            ss += __shfl_xor_sync(0xffffffffu, ss, o);
            qq += __shfl_xor_sync(0xffffffffu, qq, o);
        }
        if (t == 0) {
            float mu  = ss * (1.0f / DIM);
            float var = qq * (1.0f / DIM) - mu * mu;
            s_mu = mu;
            s_rstd = rsqrtf(var + 1e-5f);
        }
    }
    __syncthreads();
    float mu = s_mu, rstd = s_rstd;
    float4 gg = ((const float4*)gam)[t];
    float4 bb = ((const float4*)bet)[t];
    float o0 = (v.x - mu) * rstd * gg.x + bb.x;
    float o1 = (v.y - mu) * rstd * gg.y + bb.y;
    float o2 = (v.z - mu) * rstd * gg.z + bb.z;
    float o3 = (v.w - mu) * rstd * gg.w + bb.w;
    // k = 4t..4t+3 -> tile t>>3, slot j*8 + (t&7)
    float* dst = g_xn + (size_t)row * DIM + ((t >> 3) << 5) + (t & 7);
    dst[0]  = f2tf32(o0);
    dst[8]  = f2tf32(o1);
    dst[16] = f2tf32(o2);
    dst[24] = f2tf32(o3);
}

// ---------------------------------------------------------------------------
// TF32 mma.sync GEMM v3 (NT): inputs pre-rounded & pre-permuted, so the hot
// loop is pure cp.async -> frag LDS -> mma. Single 36.9KB stage; cross-CTA
// overlap (2 CTAs/SM) hides global latency.
// which==0: A=g_xn,   B=g_wq, C=g_qkv (K=1024)
// which==1: A=g_attn, B=g_wo, C=Cext  (K=512)
// ---------------------------------------------------------------------------
#define SA 36
#define NT_N 1024

__global__ void __launch_bounds__(256) gemm_mma(float* __restrict__ Cext,
                                                int K, int which) {
    __shared__ float As[128 * SA];
    __shared__ float Bs[128 * SA];

    const float* __restrict__ A = which ? g_attn : g_xn;
    const float* __restrict__ B = which ? g_wo : g_wq;
    float* __restrict__ C       = which ? Cext : g_qkv;

    const int tid  = threadIdx.x;
    const int bn   = blockIdx.x * 128;
    const int bm   = blockIdx.y * 128;
    const int warp = tid >> 5;
    const int lane = tid & 31;
    const int wm   = warp & 3;
    const int wn   = warp >> 2;
    const int r    = lane >> 2;
    const int c    = lane & 3;
    const int r0   = tid >> 3;          // 0..31 load row
    const int u    = tid & 7;           // 16B chunk within 32-k tile

    float acc[2][8][4];
    #pragma unroll
    for (int mt = 0; mt < 2; mt++)
        #pragma unroll
        for (int nt = 0; nt < 8; nt++)
            #pragma unroll
            for (int q = 0; q < 4; q++) acc[mt][nt][q] = 0.0f;

    const float* ag = A + (size_t)(bm + r0) * K + u * 4;
    const float* bg = B + (size_t)(bn + r0) * K + u * 4;
    uint32_t dA = cvta_smem(As) + (uint32_t)(r0 * SA + u * 4) * 4u;
    uint32_t dB = cvta_smem(Bs) + (uint32_t)(r0 * SA + u * 4) * 4u;

    for (int k0 = 0; k0 < K; k0 += 32) {
        #pragma unroll
        for (int p = 0; p < 4; p++) {
            asm volatile("cp.async.cg.shared.global [%0], [%1], 16;"
                         :: "r"(dA + (uint32_t)(p * 32 * SA * 4)),
                            "l"(ag + (size_t)k0 + (size_t)p * 32 * K)
                         : "memory");
            asm volatile("cp.async.cg.shared.global [%0], [%1], 16;"
                         :: "r"(dB + (uint32_t)(p * 32 * SA * 4)),
                            "l"(bg + (size_t)k0 + (size_t)p * 32 * K)
                         : "memory");
        }
        asm volatile("cp.async.commit_group;" ::: "memory");
        asm volatile("cp.async.wait_group 0;" ::: "memory");
        __syncthreads();

        float aL[2][2][4], aH[2][2][4];
        #pragma unroll
        for (int mt = 0; mt < 2; mt++) {
            int rl = wm * 32 + mt * 16 + r;
            *(float4*)aL[mt][0] = *(const float4*)&As[rl * SA + c * 8];
            *(float4*)aL[mt][1] = *(const float4*)&As[rl * SA + c * 8 + 4];
            *(float4*)aH[mt][0] = *(const float4*)&As[(rl + 8) * SA + c * 8];
            *(float4*)aH[mt][1] = *(const float4*)&As[(rl + 8) * SA + c * 8 + 4];
        }

        #pragma unroll
        for (int nt = 0; nt < 8; nt++) {
            float bb[2][4];
            int nr = wn * 64 + nt * 8 + r;
            *(float4*)bb[0] = *(const float4*)&Bs[nr * SA + c * 8];
            *(float4*)bb[1] = *(const float4*)&Bs[nr * SA + c * 8 + 4];
            #pragma unroll
            for (int mt = 0; mt < 2; mt++) {
                #pragma unroll
                for (int s = 0; s < 4; s++) {
                    int q = s >> 1, o = (s & 1) * 2;
                    mma_tf32(acc[mt][nt],
                             aL[mt][q][o], aH[mt][q][o],
                             aL[mt][q][o + 1], aH[mt][q][o + 1],
                             bb[q][o], bb[q][o + 1]);
                }
            }
        }
        __syncthreads();
    }

    #pragma unroll
    for (int mt = 0; mt < 2; mt++) {
        #pragma unroll
        for (int nt = 0; nt < 8; nt++) {
            int row = bm + wm * 32 + mt * 16 + r;
            int col = bn + wn * 64 + nt * 8 + 2 * c;
            *(float2*)&C[(size_t)row * NT_N + col] =
                make_float2(acc[mt][nt][0], acc[mt][nt][1]);
            *(float2*)&C[(size_t)(row + 8) * NT_N + col] =
                make_float2(acc[mt][nt][2], acc[mt][nt][3]);
        }
    }
}

// ---------------------------------------------------------------------------
// Tensor-core flash attention (R9 structure; epilogue now writes g_attn
// tf32-rounded + k-permuted for the out-projection GEMM).
// ---------------------------------------------------------------------------
struct AttnSmem {
    union {
        struct {
            float ks0[32][36];
            float ks1[32][36];
            float vsT[64][36];
        } kv;
        float qstage[64][68];
    } u;
    float Ss[128 * 36];
    float vstage[32][64];
    float corr[128];
    float lrow[128];
};

__global__ void __launch_bounds__(256) attn_kernel() {
    __shared__ AttnSmem sm;

    const int wi   = blockIdx.x;
    const int bh   = blockIdx.y;
    const int b    = bh >> 3;
    const int h    = bh & 7;
    const int tid  = threadIdx.x;
    const int warp = tid >> 5;
    const int lane = tid & 31;
    const int r    = lane >> 2;
    const int c    = lane & 3;
    const int row0 = warp * 16;

    const float* __restrict__ qkv = g_qkv;

    // ---------------- phase 0: q fragments (rotated, tf32) ----------------
    float qa[8][4];
    #pragma unroll
    for (int half = 0; half < 2; half++) {
        {
            int sr = tid >> 2, quad = tid & 3;
            const float* qg = qkv +
                (size_t)(b * SEQ + wi * WS + half * 64 + sr) * DIM + h * DH;
            #pragma unroll
            for (int p = 0; p < 4; p++)
                *(float4*)&sm.u.qstage[sr][p * 16 + quad * 4] =
                    *(const float4*)(qg + p * 16 + quad * 4);
        }
        __syncthreads();
        #pragma unroll
        for (int p = 0; p < 8; p++) {
            int idx = p * 256 + tid;
            int sr = idx >> 5, e = idx & 31;
            int gi = (half * 64 + sr) * DH;
            float x1 = sm.u.qstage[sr][e], x2 = sm.u.qstage[sr][e + 32];
            float c1 = g_qcs[gi + e],      s1 = g_qsn[gi + e];
            float c2 = g_qcs[gi + e + 32], s2 = g_qsn[gi + e + 32];
            sm.u.qstage[sr][e]      = f2tf32(x1 * c1 - x2 * s1);
            sm.u.qstage[sr][e + 32] = f2tf32(x2 * c2 + x1 * s2);
        }
        __syncthreads();
        if ((warp >> 2) == half) {
            int lr = (warp & 3) * 16 + r;
            #pragma unroll
            for (int kk = 0; kk < 8; kk++) {
                qa[kk][0] = sm.u.qstage[lr][kk * 8 + c];
                qa[kk][1] = sm.u.qstage[lr + 8][kk * 8 + c];
                qa[kk][2] = sm.u.qstage[lr][kk * 8 + c + 4];
                qa[kk][3] = sm.u.qstage[lr + 8][kk * 8 + c + 4];
            }
        }
        __syncthreads();
    }

    float Oacc[8][4];
    #pragma unroll
    for (int nt = 0; nt < 8; nt++)
        #pragma unroll
        for (int q = 0; q < 4; q++) Oacc[nt][q] = 0.0f;

    float m_run = NEG_INF, l_run = 0.0f;

    const uint32_t vstage_base = cvta_smem(&sm.vstage[0][0]);

    // ---------------- chunk loop ----------------
    for (int ch = 0; ch < 12; ch++) {
        int kw = wi - 1 + (ch >> 2);
        if (kw < 0 || kw >= NWIN) continue;

        // (1) prefetch raw v chunk via cp.async
        {
            int j = tid >> 3, u8 = tid & 7;
            const float* vg = qkv +
                (size_t)(b * SEQ + (wi - 1) * WS + ch * 32 + j) * DIM
                + INNER + h * DH + u8 * 8;
            uint32_t dst = vstage_base + (uint32_t)(j * 64 + u8 * 8) * 4u;
            asm volatile("cp.async.cg.shared.global [%0], [%1], 16;"
                         :: "r"(dst), "l"(vg) : "memory");
            asm volatile("cp.async.cg.shared.global [%0], [%1], 16;"
                         :: "r"(dst + 16u), "l"(vg + 4) : "memory");
            asm volatile("cp.async.commit_group;" ::: "memory");
        }

        // (2) k: direct load + fused rotation + permuted store
        #pragma unroll
        for (int p = 0; p < 4; p++) {
            int j = (tid >> 5) + p * 8;
            int e = tid & 31;
            const float* kg = qkv +
                (size_t)(b * SEQ + (wi - 1) * WS + ch * 32 + j) * DIM + h * DH;
            float x1 = kg[e], x2 = kg[e + 32];
            int gi = (ch * 32 + j) * DH;
            sm.u.kv.ks0[j][PERM(e)] =
                f2tf32(x1 * g_kcos[gi + e] - x2 * g_ksin[gi + e]);
            sm.u.kv.ks1[j][PERM(e)] =
                f2tf32(x2 * g_kcos[gi + e + 32] + x1 * g_ksin[gi + e + 32]);
        }
        __syncthreads();   // S1

        // (3) S = Q.K^T
        float Sacc[4][4];
        #pragma unroll
        for (int nt = 0; nt < 4; nt++)
            #pragma unroll
            for (int q = 0; q < 4; q++) Sacc[nt][q] = 0.0f;
        #pragma unroll
        for (int nt = 0; nt < 4; nt++) {
            float bbA[2][4], bbB[2][4];
            int nr = nt * 8 + r;
            *(float4*)bbA[0] = *(const float4*)&sm.u.kv.ks0[nr][c * 8];
            *(float4*)bbA[1] = *(const float4*)&sm.u.kv.ks0[nr][c * 8 + 4];
            *(float4*)bbB[0] = *(const float4*)&sm.u.kv.ks1[nr][c * 8];
            *(float4*)bbB[1] = *(const float4*)&sm.u.kv.ks1[nr][c * 8 + 4];
            #pragma unroll
            for (int s = 0; s < 4; s++) {
                int q = s >> 1, o = (s & 1) * 2;
                mma_tf32(Sacc[nt], qa[s][0], qa[s][1], qa[s][2], qa[s][3],
                         bbA[q][o], bbA[q][o + 1]);
            }
            #pragma unroll
            for (int s = 0; s < 4; s++) {
                int q = s >> 1, o = (s & 1) * 2;
                mma_tf32(Sacc[nt], qa[4 + s][0], qa[4 + s][1],
                         qa[4 + s][2], qa[4 + s][3],
                         bbB[q][o], bbB[q][o + 1]);
            }
        }
        #pragma unroll
        for (int nt = 0; nt < 4; nt++) {
            int j0 = nt * 8 + 2 * c;
            sm.Ss[(row0 + r) * 36 + PERM(j0)]         = Sacc[nt][0];
            sm.Ss[(row0 + r) * 36 + PERM(j0 + 1)]     = Sacc[nt][1];
            sm.Ss[(row0 + r + 8) * 36 + PERM(j0)]     = Sacc[nt][2];
            sm.Ss[(row0 + r + 8) * 36 + PERM(j0 + 1)] = Sacc[nt][3];
        }
        asm volatile("cp.async.wait_group 0;" ::: "memory");
        __syncthreads();   // S2

        // (4a) softmax on threads 0-127
        if (tid < 128) {
            int row = tid;
            int jlo = row - ch * 32;       if (jlo < 0)  jlo = 0;
            int jhi = row + 256 - ch * 32; if (jhi > 31) jhi = 31;
            float cr = 1.0f;
            if (jlo <= jhi) {
                float mc = NEG_INF;
                for (int j = jlo; j <= jhi; j++)
                    mc = fmaxf(mc, sm.Ss[row * 36 + PERM(j)]);
                float mnew = fmaxf(m_run, mc);
                cr = __expf(m_run - mnew);
                float sum = 0.0f;
                #pragma unroll 4
                for (int j = 0; j < 32; j++) {
                    float p = 0.0f;
                    if (j >= jlo && j <= jhi) {
                        p = __expf(sm.Ss[row * 36 + PERM(j)] - mnew);
                        sum += p;
                    }
                    sm.Ss[row * 36 + PERM(j)] = f2tf32(p);
                }
                l_run = l_run * cr + sum;
                m_run = mnew;
            } else {
                #pragma unroll 4
                for (int j = 0; j < 32; j++)
                    sm.Ss[row * 36 + PERM(j)] = 0.0f;
            }
            sm.corr[row] = cr;
        } else {
            // (4b) concurrent v transpose+permute
            int t2 = tid - 128;
            #pragma unroll
            for (int p = 0; p < 16; p++) {
                int idx = p * 128 + t2;
                int j = idx >> 6, e = idx & 63;
                sm.u.kv.vsT[e][PERM(j)] = f2tf32(sm.vstage[j][e]);
            }
        }
        __syncthreads();   // S3

        // (5) O = O*corr + P.V
        float cr0 = sm.corr[row0 + r], cr1 = sm.corr[row0 + r + 8];
        #pragma unroll
        for (int nt = 0; nt < 8; nt++) {
            Oacc[nt][0] *= cr0; Oacc[nt][1] *= cr0;
            Oacc[nt][2] *= cr1; Oacc[nt][3] *= cr1;
        }
        float paL[2][4], paH[2][4];
        *(float4*)paL[0] = *(const float4*)&sm.Ss[(row0 + r) * 36 + c * 8];
        *(float4*)paL[1] = *(const float4*)&sm.Ss[(row0 + r) * 36 + c * 8 + 4];
        *(float4*)paH[0] = *(const float4*)&sm.Ss[(row0 + r + 8) * 36 + c * 8];
        *(float4*)paH[1] = *(const float4*)&sm.Ss[(row0 + r + 8) * 36 + c * 8 + 4];
        #pragma unroll
        for (int nt = 0; nt < 8; nt++) {
            float bb[2][4];
            int nr = nt * 8 + r;
            *(float4*)bb[0] = *(const float4*)&sm.u.kv.vsT[nr][c * 8];
            *(float4*)bb[1] = *(const float4*)&sm.u.kv.vsT[nr][c * 8 + 4];
            #pragma unroll
            for (int s = 0; s < 4; s++) {
                int q = s >> 1, o = (s & 1) * 2;
                mma_tf32(Oacc[nt], paL[q][o], paH[q][o],
                         paL[q][o + 1], paH[q][o + 1],
                         bb[q][o], bb[q][o + 1]);
            }
        }
    }

    // ---------------- finalize: write g_attn tf32-rounded + permuted ------
    __syncthreads();
    if (tid < 128) sm.lrow[tid] = l_run;
    __syncthreads();
    float inv0 = 1.0f / sm.lrow[row0 + r];
    float inv1 = 1.0f / sm.lrow[row0 + r + 8];
    float* ob = g_attn + (size_t)(b * SEQ + wi * WS) * INNER + h * DH;
    #pragma unroll
    for (int nt = 0; nt < 8; nt++) {
        #pragma unroll
        for (int e = 0; e < 2; e++) {
            int col = nt * 8 + 2 * c + e;   // 0..63 within head
            int slot = ((col >> 5) << 5) + ((col & 3) << 3) + ((col >> 2) & 7);
            ob[(size_t)(row0 + r) * INNER + slot] =
                f2tf32(Oacc[nt][e] * inv0);
            ob[(size_t)(row0 + r + 8) * INNER + slot] =
                f2tf32(Oacc[nt][2 + e] * inv1);
        }
    }
}

// ---------------------------------------------------------------------------
// Launch: pure kernel launches, zero runtime API calls.
// ---------------------------------------------------------------------------
extern "C" void kernel_launch(void* const* d_in, const int* in_sizes, int n_in,
                              void* d_out, int out_size) {
    const float* x     = (const float*)d_in[0];
    const float* ln_g  = (const float*)d_in[1];
    const float* ln_b  = (const float*)d_in[2];
    const float* w_qkv = (const float*)d_in[3];
    const float* w_out = (const float*)d_in[4];
    float* out = (float*)d_out;

    rope_precompute_kernel<<<(JLEN * DH + 255) / 256, 256>>>();
    wperm_kernel<<<(DIM * DIM + 255) / 256, 256>>>(w_qkv, w_out);
    ln_kernel<<<M_ROWS, 256>>>(x, ln_g, ln_b);

    // qkv = xn @ w_qkv^T  (K=1024)
    gemm_mma<<<dim3(NT_N / 128, M_ROWS / 128), 256>>>(nullptr, DIM, 0);

    attn_kernel<<<dim3(NWIN, BATCH * HEADS), 256>>>();

    // out = attn @ w_out^T (K=512)
    gemm_mma<<<dim3(NT_N / 128, M_ROWS / 128), 256>>>(out, INNER, 1);
}

// round 11
// speedup vs baseline: 1.2352x; 1.2352x over previous
#include <cuda_runtime.h>
#include <cuda_bf16.h>
#include <math.h>
#include <stdint.h>

// ---------------------------------------------------------------------------
// Problem constants
// ---------------------------------------------------------------------------
#define BATCH 4
#define SEQ   4096
#define DIM   1024
#define HEADS 8
#define DH    64
#define WS    128
#define NWIN  32
#define INNER 512
#define JLEN  384
#define M_ROWS (BATCH * SEQ)   // 16384

#define NEG_INF (-3.402823466e+38f)

// ---------------------------------------------------------------------------
// Scratch (device globals; kernel_launch makes NO runtime API calls)
// g_xn / g_attn / g_wq / g_wo hold tf32-rounded, k-permuted data:
//   within each 32-k tile, element k lives at slot (k&3)*8 + (k>>2).
// ---------------------------------------------------------------------------
__device__ float g_xn  [M_ROWS * DIM];
__device__ float g_qkv [M_ROWS * DIM];      // normal layout (attn reads it)
__device__ float g_attn[M_ROWS * INNER];
__device__ float g_wq  [DIM * DIM];
__device__ float g_wo  [DIM * INNER];
__device__ float g_kcos[JLEN * DH];
__device__ float g_ksin[JLEN * DH];
__device__ float g_qcs [WS * DH];
__device__ float g_qsn [WS * DH];

// ---------------------------------------------------------------------------
// Helpers
// ---------------------------------------------------------------------------
__device__ __forceinline__ float f2tf32(float x) {
    uint32_t y;
    asm("cvt.rna.tf32.f32 %0, %1;" : "=r"(y) : "f"(x));
    return __uint_as_float(y);
}

__device__ __forceinline__ void mma_tf32(float* d,
                                         float a0, float a1,
                                         float a2, float a3,
                                         float b0, float b1) {
    asm volatile(
        "mma.sync.aligned.m16n8k8.row.col.f32.tf32.tf32.f32 "
        "{%0,%1,%2,%3}, {%4,%5,%6,%7}, {%8,%9}, {%0,%1,%2,%3};\n"
        : "+f"(d[0]), "+f"(d[1]), "+f"(d[2]), "+f"(d[3])
        : "r"(__float_as_uint(a0)), "r"(__float_as_uint(a1)),
          "r"(__float_as_uint(a2)), "r"(__float_as_uint(a3)),
          "r"(__float_as_uint(b0)), "r"(__float_as_uint(b1)));
}

__device__ __forceinline__ uint32_t cvta_smem(const void* p) {
    uint32_t a;
    asm("{ .reg .u64 t; cvta.to.shared.u64 t, %1; cvt.u32.u64 %0, t; }"
        : "=r"(a) : "l"(p));
    return a;
}

#define PERM(j) (((j) & 3) * 8 + ((j) >> 2))
// global k-permuted slot within a row (tile-local PERM, tile-preserving)
#define GSLOT(k) ((((k) >> 5) << 5) + (((k) & 3) << 3) + (((k) >> 2) & 7))

// ---------------------------------------------------------------------------
// Rotary / xpos coefficient precompute
// ---------------------------------------------------------------------------
__global__ void rope_precompute_kernel() {
    int idx = blockIdx.x * blockDim.x + threadIdx.x;
    if (idx >= JLEN * DH) return;
    int t = idx / DH;
    int e = idx % DH;
    int f = e & 31;
    float invf = powf(10000.0f, -(2.0f * (float)f) / (float)DH);
    float ang  = (float)t * invf;
    float sb   = (2.0f * (float)f + 0.4f * (float)DH) / (1.4f * (float)DH);
    float pw   = ((float)t - (float)(JLEN / 2)) / (float)(WS / 2);
    float sc   = powf(sb, pw);
    float c = cosf(ang), s = sinf(ang);
    g_kcos[idx] = c / sc;
    g_ksin[idx] = s / sc;
    if (t >= JLEN - WS) {
        int i = t - (JLEN - WS);
        g_qcs[i * DH + e] = c * sc * 0.125f;
        g_qsn[i * DH + e] = s * sc * 0.125f;
    }
}

// ---------------------------------------------------------------------------
// Weight pre-permute + tf32 round (one-off, ~1.5M elems)
// ---------------------------------------------------------------------------
__global__ void wperm_kernel(const float* __restrict__ w_qkv,
                             const float* __restrict__ w_out) {
    int idx = blockIdx.x * blockDim.x + threadIdx.x;
    if (idx < DIM * DIM) {
        int row = idx >> 10, k = idx & 1023;
        g_wq[(size_t)row * DIM + GSLOT(k)] = f2tf32(w_qkv[idx]);
    }
    if (idx < DIM * INNER) {
        int row = idx / INNER, k = idx % INNER;
        g_wo[(size_t)row * INNER + GSLOT(k)] = f2tf32(w_out[idx]);
    }
}

// ---------------------------------------------------------------------------
// LayerNorm -> g_xn (tf32-rounded, k-permuted)
// ---------------------------------------------------------------------------
__global__ void __launch_bounds__(256) ln_kernel(const float* __restrict__ x,
                                                 const float* __restrict__ gam,
                                                 const float* __restrict__ bet) {
    __shared__ float red [8];
    __shared__ float red2[8];
    __shared__ float s_mu, s_rstd;
    int row = blockIdx.x;
    int t = threadIdx.x;
    float4 v = ((const float4*)(x + (size_t)row * DIM))[t];
    float s  = v.x + v.y + v.z + v.w;
    float sq = v.x * v.x + v.y * v.y + v.z * v.z + v.w * v.w;
    #pragma unroll
    for (int o = 16; o > 0; o >>= 1) {
        s  += __shfl_xor_sync(0xffffffffu, s,  o);
        sq += __shfl_xor_sync(0xffffffffu, sq, o);
    }
    if ((t & 31) == 0) { red[t >> 5] = s; red2[t >> 5] = sq; }
    __syncthreads();
    if (t < 32) {
        float ss = (t < 8) ? red [t] : 0.0f;
        float qq = (t < 8) ? red2[t] : 0.0f;
        #pragma unroll
        for (int o = 4; o > 0; o >>= 1) {
            ss += __shfl_xor_sync(0xffffffffu, ss, o);
            qq += __shfl_xor_sync(0xffffffffu, qq, o);
        }
        if (t == 0) {
            float mu  = ss * (1.0f / DIM);
            float var = qq * (1.0f / DIM) - mu * mu;
            s_mu = mu;
            s_rstd = rsqrtf(var + 1e-5f);
        }
    }
    __syncthreads();
    float mu = s_mu, rstd = s_rstd;
    float4 gg = ((const float4*)gam)[t];
    float4 bb = ((const float4*)bet)[t];
    float o0 = (v.x - mu) * rstd * gg.x + bb.x;
    float o1 = (v.y - mu) * rstd * gg.y + bb.y;
    float o2 = (v.z - mu) * rstd * gg.z + bb.z;
    float o3 = (v.w - mu) * rstd * gg.w + bb.w;
    // k = 4t..4t+3 -> tile t>>3, slot j*8 + (t&7)
    float* dst = g_xn + (size_t)row * DIM + ((t >> 3) << 5) + (t & 7);
    dst[0]  = f2tf32(o0);
    dst[8]  = f2tf32(o1);
    dst[16] = f2tf32(o2);
    dst[24] = f2tf32(o3);
}

// ---------------------------------------------------------------------------
// TF32 mma.sync GEMM v3b (NT): pre-rounded & pre-permuted inputs; hot loop is
// pure cp.async -> frag LDS -> mma. __launch_bounds__(256,2) forces <=128
// regs so 2 CTAs/SM co-reside: one CTA's load/wait phase overlaps the other's
// mma phase (this clause was dropped in R10 -> 1 CTA/SM -> 425us regression).
// which==0: A=g_xn,   B=g_wq, C=g_qkv (K=1024)
// which==1: A=g_attn, B=g_wo, C=Cext  (K=512)
// ---------------------------------------------------------------------------
#define SA 36
#define NT_N 1024

__global__ void __launch_bounds__(256, 2) gemm_mma(float* __restrict__ Cext,
                                                   int K, int which) {
    __shared__ float As[128 * SA];
    __shared__ float Bs[128 * SA];

    const float* __restrict__ A = which ? g_attn : g_xn;
    const float* __restrict__ B = which ? g_wo : g_wq;
    float* __restrict__ C       = which ? Cext : g_qkv;

    const int tid  = threadIdx.x;
    const int bn   = blockIdx.x * 128;
    const int bm   = blockIdx.y * 128;
    const int warp = tid >> 5;
    const int lane = tid & 31;
    const int wm   = warp & 3;
    const int wn   = warp >> 2;
    const int r    = lane >> 2;
    const int c    = lane & 3;
    const int r0   = tid >> 3;          // 0..31 load row
    const int u    = tid & 7;           // 16B chunk within 32-k tile

    float acc[2][8][4];
    #pragma unroll
    for (int mt = 0; mt < 2; mt++)
        #pragma unroll
        for (int nt = 0; nt < 8; nt++)
            #pragma unroll
            for (int q = 0; q < 4; q++) acc[mt][nt][q] = 0.0f;

    const float* ag = A + (size_t)(bm + r0) * K + u * 4;
    const float* bg = B + (size_t)(bn + r0) * K + u * 4;
    uint32_t dA = cvta_smem(As) + (uint32_t)(r0 * SA + u * 4) * 4u;
    uint32_t dB = cvta_smem(Bs) + (uint32_t)(r0 * SA + u * 4) * 4u;

    for (int k0 = 0; k0 < K; k0 += 32) {
        #pragma unroll
        for (int p = 0; p < 4; p++) {
            asm volatile("cp.async.cg.shared.global [%0], [%1], 16;"
                         :: "r"(dA + (uint32_t)(p * 32 * SA * 4)),
                            "l"(ag + (size_t)k0 + (size_t)p * 32 * K)
                         : "memory");
            asm volatile("cp.async.cg.shared.global [%0], [%1], 16;"
                         :: "r"(dB + (uint32_t)(p * 32 * SA * 4)),
                            "l"(bg + (size_t)k0 + (size_t)p * 32 * K)
                         : "memory");
        }
        asm volatile("cp.async.commit_group;" ::: "memory");
        asm volatile("cp.async.wait_group 0;" ::: "memory");
        __syncthreads();

        float aL[2][2][4], aH[2][2][4];
        #pragma unroll
        for (int mt = 0; mt < 2; mt++) {
            int rl = wm * 32 + mt * 16 + r;
            *(float4*)aL[mt][0] = *(const float4*)&As[rl * SA + c * 8];
            *(float4*)aL[mt][1] = *(const float4*)&As[rl * SA + c * 8 + 4];
            *(float4*)aH[mt][0] = *(const float4*)&As[(rl + 8) * SA + c * 8];
            *(float4*)aH[mt][1] = *(const float4*)&As[(rl + 8) * SA + c * 8 + 4];
        }

        #pragma unroll
        for (int nt = 0; nt < 8; nt++) {
            float bb[2][4];
            int nr = wn * 64 + nt * 8 + r;
            *(float4*)bb[0] = *(const float4*)&Bs[nr * SA + c * 8];
            *(float4*)bb[1] = *(const float4*)&Bs[nr * SA + c * 8 + 4];
            #pragma unroll
            for (int mt = 0; mt < 2; mt++) {
                #pragma unroll
                for (int s = 0; s < 4; s++) {
                    int q = s >> 1, o = (s & 1) * 2;
                    mma_tf32(acc[mt][nt],
                             aL[mt][q][o], aH[mt][q][o],
                             aL[mt][q][o + 1], aH[mt][q][o + 1],
                             bb[q][o], bb[q][o + 1]);
                }
            }
        }
        __syncthreads();
    }

    #pragma unroll
    for (int mt = 0; mt < 2; mt++) {
        #pragma unroll
        for (int nt = 0; nt < 8; nt++) {
            int row = bm + wm * 32 + mt * 16 + r;
            int col = bn + wn * 64 + nt * 8 + 2 * c;
            *(float2*)&C[(size_t)row * NT_N + col] =
                make_float2(acc[mt][nt][0], acc[mt][nt][1]);
            *(float2*)&C[(size_t)(row + 8) * NT_N + col] =
                make_float2(acc[mt][nt][2], acc[mt][nt][3]);
        }
    }
}

// ---------------------------------------------------------------------------
// Tensor-core flash attention (unchanged from R10; epilogue writes g_attn
// tf32-rounded + k-permuted for the out-projection GEMM).
// ---------------------------------------------------------------------------
struct AttnSmem {
    union {
        struct {
            float ks0[32][36];
            float ks1[32][36];
            float vsT[64][36];
        } kv;
        float qstage[64][68];
    } u;
    float Ss[128 * 36];
    float vstage[32][64];
    float corr[128];
    float lrow[128];
};

__global__ void __launch_bounds__(256) attn_kernel() {
    __shared__ AttnSmem sm;

    const int wi   = blockIdx.x;
    const int bh   = blockIdx.y;
    const int b    = bh >> 3;
    const int h    = bh & 7;
    const int tid  = threadIdx.x;
    const int warp = tid >> 5;
    const int lane = tid & 31;
    const int r    = lane >> 2;
    const int c    = lane & 3;
    const int row0 = warp * 16;

    const float* __restrict__ qkv = g_qkv;

    // ---------------- phase 0: q fragments (rotated, tf32) ----------------
    float qa[8][4];
    #pragma unroll
    for (int half = 0; half < 2; half++) {
        {
            int sr = tid >> 2, quad = tid & 3;
            const float* qg = qkv +
                (size_t)(b * SEQ + wi * WS + half * 64 + sr) * DIM + h * DH;
            #pragma unroll
            for (int p = 0; p < 4; p++)
                *(float4*)&sm.u.qstage[sr][p * 16 + quad * 4] =
                    *(const float4*)(qg + p * 16 + quad * 4);
        }
        __syncthreads();
        #pragma unroll
        for (int p = 0; p < 8; p++) {
            int idx = p * 256 + tid;
            int sr = idx >> 5, e = idx & 31;
            int gi = (half * 64 + sr) * DH;
            float x1 = sm.u.qstage[sr][e], x2 = sm.u.qstage[sr][e + 32];
            float c1 = g_qcs[gi + e],      s1 = g_qsn[gi + e];
            float c2 = g_qcs[gi + e + 32], s2 = g_qsn[gi + e + 32];
            sm.u.qstage[sr][e]      = f2tf32(x1 * c1 - x2 * s1);
            sm.u.qstage[sr][e + 32] = f2tf32(x2 * c2 + x1 * s2);
        }
        __syncthreads();
        if ((warp >> 2) == half) {
            int lr = (warp & 3) * 16 + r;
            #pragma unroll
            for (int kk = 0; kk < 8; kk++) {
                qa[kk][0] = sm.u.qstage[lr][kk * 8 + c];
                qa[kk][1] = sm.u.qstage[lr + 8][kk * 8 + c];
                qa[kk][2] = sm.u.qstage[lr][kk * 8 + c + 4];
                qa[kk][3] = sm.u.qstage[lr + 8][kk * 8 + c + 4];
            }
        }
        __syncthreads();
    }

    float Oacc[8][4];
    #pragma unroll
    for (int nt = 0; nt < 8; nt++)
        #pragma unroll
        for (int q = 0; q < 4; q++) Oacc[nt][q] = 0.0f;

    float m_run = NEG_INF, l_run = 0.0f;

    const uint32_t vstage_base = cvta_smem(&sm.vstage[0][0]);

    // ---------------- chunk loop ----------------
    for (int ch = 0; ch < 12; ch++) {
        int kw = wi - 1 + (ch >> 2);
        if (kw < 0 || kw >= NWIN) continue;

        // (1) prefetch raw v chunk via cp.async
        {
            int j = tid >> 3, u8 = tid & 7;
            const float* vg = qkv +
                (size_t)(b * SEQ + (wi - 1) * WS + ch * 32 + j) * DIM
                + INNER + h * DH + u8 * 8;
            uint32_t dst = vstage_base + (uint32_t)(j * 64 + u8 * 8) * 4u;
            asm volatile("cp.async.cg.shared.global [%0], [%1], 16;"
                         :: "r"(dst), "l"(vg) : "memory");
            asm volatile("cp.async.cg.shared.global [%0], [%1], 16;"
                         :: "r"(dst + 16u), "l"(vg + 4) : "memory");
            asm volatile("cp.async.commit_group;" ::: "memory");
        }

        // (2) k: direct load + fused rotation + permuted store
        #pragma unroll
        for (int p = 0; p < 4; p++) {
            int j = (tid >> 5) + p * 8;
            int e = tid & 31;
            const float* kg = qkv +
                (size_t)(b * SEQ + (wi - 1) * WS + ch * 32 + j) * DIM + h * DH;
            float x1 = kg[e], x2 = kg[e + 32];
            int gi = (ch * 32 + j) * DH;
            sm.u.kv.ks0[j][PERM(e)] =
                f2tf32(x1 * g_kcos[gi + e] - x2 * g_ksin[gi + e]);
            sm.u.kv.ks1[j][PERM(e)] =
                f2tf32(x2 * g_kcos[gi + e + 32] + x1 * g_ksin[gi + e + 32]);
        }
        __syncthreads();   // S1

        // (3) S = Q.K^T
        float Sacc[4][4];
        #pragma unroll
        for (int nt = 0; nt < 4; nt++)
            #pragma unroll
            for (int q = 0; q < 4; q++) Sacc[nt][q] = 0.0f;
        #pragma unroll
        for (int nt = 0; nt < 4; nt++) {
            float bbA[2][4], bbB[2][4];
            int nr = nt * 8 + r;
            *(float4*)bbA[0] = *(const float4*)&sm.u.kv.ks0[nr][c * 8];
            *(float4*)bbA[1] = *(const float4*)&sm.u.kv.ks0[nr][c * 8 + 4];
            *(float4*)bbB[0] = *(const float4*)&sm.u.kv.ks1[nr][c * 8];
            *(float4*)bbB[1] = *(const float4*)&sm.u.kv.ks1[nr][c * 8 + 4];
            #pragma unroll
            for (int s = 0; s < 4; s++) {
                int q = s >> 1, o = (s & 1) * 2;
                mma_tf32(Sacc[nt], qa[s][0], qa[s][1], qa[s][2], qa[s][3],
                         bbA[q][o], bbA[q][o + 1]);
            }
            #pragma unroll
            for (int s = 0; s < 4; s++) {
                int q = s >> 1, o = (s & 1) * 2;
                mma_tf32(Sacc[nt], qa[4 + s][0], qa[4 + s][1],
                         qa[4 + s][2], qa[4 + s][3],
                         bbB[q][o], bbB[q][o + 1]);
            }
        }
        #pragma unroll
        for (int nt = 0; nt < 4; nt++) {
            int j0 = nt * 8 + 2 * c;
            sm.Ss[(row0 + r) * 36 + PERM(j0)]         = Sacc[nt][0];
            sm.Ss[(row0 + r) * 36 + PERM(j0 + 1)]     = Sacc[nt][1];
            sm.Ss[(row0 + r + 8) * 36 + PERM(j0)]     = Sacc[nt][2];
            sm.Ss[(row0 + r + 8) * 36 + PERM(j0 + 1)] = Sacc[nt][3];
        }
        asm volatile("cp.async.wait_group 0;" ::: "memory");
        __syncthreads();   // S2

        // (4a) softmax on threads 0-127
        if (tid < 128) {
            int row = tid;
            int jlo = row - ch * 32;       if (jlo < 0)  jlo = 0;
            int jhi = row + 256 - ch * 32; if (jhi > 31) jhi = 31;
            float cr = 1.0f;
            if (jlo <= jhi) {
                float mc = NEG_INF;
                for (int j = jlo; j <= jhi; j++)
                    mc = fmaxf(mc, sm.Ss[row * 36 + PERM(j)]);
                float mnew = fmaxf(m_run, mc);
                cr = __expf(m_run - mnew);
                float sum = 0.0f;
                #pragma unroll 4
                for (int j = 0; j < 32; j++) {
                    float p = 0.0f;
                    if (j >= jlo && j <= jhi) {
                        p = __expf(sm.Ss[row * 36 + PERM(j)] - mnew);
                        sum += p;
                    }
                    sm.Ss[row * 36 + PERM(j)] = f2tf32(p);
                }
                l_run = l_run * cr + sum;
                m_run = mnew;
            } else {
                #pragma unroll 4
                for (int j = 0; j < 32; j++)
                    sm.Ss[row * 36 + PERM(j)] = 0.0f;
            }
            sm.corr[row] = cr;
        } else {
            // (4b) concurrent v transpose+permute
            int t2 = tid - 128;
            #pragma unroll
            for (int p = 0; p < 16; p++) {
                int idx = p * 128 + t2;
                int j = idx >> 6, e = idx & 63;
                sm.u.kv.vsT[e][PERM(j)] = f2tf32(sm.vstage[j][e]);
            }
        }
        __syncthreads();   // S3

        // (5) O = O*corr + P.V
        float cr0 = sm.corr[row0 + r], cr1 = sm.corr[row0 + r + 8];
        #pragma unroll
        for (int nt = 0; nt < 8; nt++) {
            Oacc[nt][0] *= cr0; Oacc[nt][1] *= cr0;
            Oacc[nt][2] *= cr1; Oacc[nt][3] *= cr1;
        }
        float paL[2][4], paH[2][4];
        *(float4*)paL[0] = *(const float4*)&sm.Ss[(row0 + r) * 36 + c * 8];
        *(float4*)paL[1] = *(const float4*)&sm.Ss[(row0 + r) * 36 + c * 8 + 4];
        *(float4*)paH[0] = *(const float4*)&sm.Ss[(row0 + r + 8) * 36 + c * 8];
        *(float4*)paH[1] = *(const float4*)&sm.Ss[(row0 + r + 8) * 36 + c * 8 + 4];
        #pragma unroll
        for (int nt = 0; nt < 8; nt++) {
            float bb[2][4];
            int nr = nt * 8 + r;
            *(float4*)bb[0] = *(const float4*)&sm.u.kv.vsT[nr][c * 8];
            *(float4*)bb[1] = *(const float4*)&sm.u.kv.vsT[nr][c * 8 + 4];
            #pragma unroll
            for (int s = 0; s < 4; s++) {
                int q = s >> 1, o = (s & 1) * 2;
                mma_tf32(Oacc[nt], paL[q][o], paH[q][o],
                         paL[q][o + 1], paH[q][o + 1],
                         bb[q][o], bb[q][o + 1]);
            }
        }
    }

    // ---------------- finalize: write g_attn tf32-rounded + permuted ------
    __syncthreads();
    if (tid < 128) sm.lrow[tid] = l_run;
    __syncthreads();
    float inv0 = 1.0f / sm.lrow[row0 + r];
    float inv1 = 1.0f / sm.lrow[row0 + r + 8];
    float* ob = g_attn + (size_t)(b * SEQ + wi * WS) * INNER + h * DH;
    #pragma unroll
    for (int nt = 0; nt < 8; nt++) {
        #pragma unroll
        for (int e = 0; e < 2; e++) {
            int col = nt * 8 + 2 * c + e;   // 0..63 within head
            int slot = ((col >> 5) << 5) + ((col & 3) << 3) + ((col >> 2) & 7);
            ob[(size_t)(row0 + r) * INNER + slot] =
                f2tf32(Oacc[nt][e] * inv0);
            ob[(size_t)(row0 + r + 8) * INNER + slot] =
                f2tf32(Oacc[nt][2 + e] * inv1);
        }
    }
}

// ---------------------------------------------------------------------------
// Launch: pure kernel launches, zero runtime API calls.
// ---------------------------------------------------------------------------
extern "C" void kernel_launch(void* const* d_in, const int* in_sizes, int n_in,
                              void* d_out, int out_size) {
    const float* x     = (const float*)d_in[0];
    const float* ln_g  = (const float*)d_in[1];
    const float* ln_b  = (const float*)d_in[2];
    const float* w_qkv = (const float*)d_in[3];
    const float* w_out = (const float*)d_in[4];
    float* out = (float*)d_out;

    rope_precompute_kernel<<<(JLEN * DH + 255) / 256, 256>>>();
    wperm_kernel<<<(DIM * DIM + 255) / 256, 256>>>(w_qkv, w_out);
    ln_kernel<<<M_ROWS, 256>>>(x, ln_g, ln_b);

    // qkv = xn @ w_qkv^T  (K=1024)
    gemm_mma<<<dim3(NT_N / 128, M_ROWS / 128), 256>>>(nullptr, DIM, 0);

    attn_kernel<<<dim3(NWIN, BATCH * HEADS), 256>>>();

    // out = attn @ w_out^T (K=512)
    gemm_mma<<<dim3(NT_N / 128, M_ROWS / 128), 256>>>(out, INNER, 1);
}

// round 12
// speedup vs baseline: 1.2403x; 1.0042x over previous
#include <cuda_runtime.h>
#include <cuda_bf16.h>
#include <math.h>
#include <stdint.h>

// ---------------------------------------------------------------------------
// Problem constants
// ---------------------------------------------------------------------------
#define BATCH 4
#define SEQ   4096
#define DIM   1024
#define HEADS 8
#define DH    64
#define WS    128
#define NWIN  32
#define INNER 512
#define JLEN  384
#define M_ROWS (BATCH * SEQ)   // 16384

#define NEG_INF (-3.402823466e+38f)

// ---------------------------------------------------------------------------
// Scratch. g_xn / g_attn / g_wq / g_wo hold tf32-rounded data in perm16
// layout: within each 16-k tile, element k lives at slot (k&3)*4+((k>>2)&3).
// ---------------------------------------------------------------------------
__device__ float g_xn  [M_ROWS * DIM];
__device__ float g_qkv [M_ROWS * DIM];      // normal layout (attn reads it)
__device__ float g_attn[M_ROWS * INNER];
__device__ float g_wq  [DIM * DIM];
__device__ float g_wo  [DIM * INNER];
__device__ float g_kcos[JLEN * DH];
__device__ float g_ksin[JLEN * DH];
__device__ float g_qcs [WS * DH];
__device__ float g_qsn [WS * DH];

// ---------------------------------------------------------------------------
// Helpers
// ---------------------------------------------------------------------------
__device__ __forceinline__ float f2tf32(float x) {
    uint32_t y;
    asm("cvt.rna.tf32.f32 %0, %1;" : "=r"(y) : "f"(x));
    return __uint_as_float(y);
}

__device__ __forceinline__ void mma_tf32(float* d,
                                         float a0, float a1,
                                         float a2, float a3,
                                         float b0, float b1) {
    asm volatile(
        "mma.sync.aligned.m16n8k8.row.col.f32.tf32.tf32.f32 "
        "{%0,%1,%2,%3}, {%4,%5,%6,%7}, {%8,%9}, {%0,%1,%2,%3};\n"
        : "+f"(d[0]), "+f"(d[1]), "+f"(d[2]), "+f"(d[3])
        : "r"(__float_as_uint(a0)), "r"(__float_as_uint(a1)),
          "r"(__float_as_uint(a2)), "r"(__float_as_uint(a3)),
          "r"(__float_as_uint(b0)), "r"(__float_as_uint(b1)));
}

__device__ __forceinline__ uint32_t cvta_smem(const void* p) {
    uint32_t a;
    asm("{ .reg .u64 t; cvta.to.shared.u64 t, %1; cvt.u32.u64 %0, t; }"
        : "=r"(a) : "l"(p));
    return a;
}

#define PERM(j)    (((j) & 3) * 8 + ((j) >> 2))                 // 32-k (attn)
#define GSLOT16(k) ((((k) >> 4) << 4) + (((k) & 3) << 2) + (((k) >> 2) & 3))

// ---------------------------------------------------------------------------
// Rotary / xpos coefficient precompute
// ---------------------------------------------------------------------------
__global__ void rope_precompute_kernel() {
    int idx = blockIdx.x * blockDim.x + threadIdx.x;
    if (idx >= JLEN * DH) return;
    int t = idx / DH;
    int e = idx % DH;
    int f = e & 31;
    float invf = powf(10000.0f, -(2.0f * (float)f) / (float)DH);
    float ang  = (float)t * invf;
    float sb   = (2.0f * (float)f + 0.4f * (float)DH) / (1.4f * (float)DH);
    float pw   = ((float)t - (float)(JLEN / 2)) / (float)(WS / 2);
    float sc   = powf(sb, pw);
    float c = cosf(ang), s = sinf(ang);
    g_kcos[idx] = c / sc;
    g_ksin[idx] = s / sc;
    if (t >= JLEN - WS) {
        int i = t - (JLEN - WS);
        g_qcs[i * DH + e] = c * sc * 0.125f;
        g_qsn[i * DH + e] = s * sc * 0.125f;
    }
}

// ---------------------------------------------------------------------------
// Weight pre-permute + tf32 round (one-off)
// ---------------------------------------------------------------------------
__global__ void wperm_kernel(const float* __restrict__ w_qkv,
                             const float* __restrict__ w_out) {
    int idx = blockIdx.x * blockDim.x + threadIdx.x;
    if (idx < DIM * DIM) {
        int row = idx >> 10, k = idx & 1023;
        g_wq[(size_t)row * DIM + GSLOT16(k)] = f2tf32(w_qkv[idx]);
    }
    if (idx < DIM * INNER) {
        int row = idx / INNER, k = idx % INNER;
        g_wo[(size_t)row * INNER + GSLOT16(k)] = f2tf32(w_out[idx]);
    }
}

// ---------------------------------------------------------------------------
// LayerNorm -> g_xn (tf32-rounded, perm16)
// k = 4t+j -> tile t>>2, slot j*4 + (t&3)
// ---------------------------------------------------------------------------
__global__ void __launch_bounds__(256) ln_kernel(const float* __restrict__ x,
                                                 const float* __restrict__ gam,
                                                 const float* __restrict__ bet) {
    __shared__ float red [8];
    __shared__ float red2[8];
    __shared__ float s_mu, s_rstd;
    int row = blockIdx.x;
    int t = threadIdx.x;
    float4 v = ((const float4*)(x + (size_t)row * DIM))[t];
    float s  = v.x + v.y + v.z + v.w;
    float sq = v.x * v.x + v.y * v.y + v.z * v.z + v.w * v.w;
    #pragma unroll
    for (int o = 16; o > 0; o >>= 1) {
        s  += __shfl_xor_sync(0xffffffffu, s,  o);
        sq += __shfl_xor_sync(0xffffffffu, sq, o);
    }
    if ((t & 31) == 0) { red[t >> 5] = s; red2[t >> 5] = sq; }
    __syncthreads();
    if (t < 32) {
        float ss = (t < 8) ? red [t] : 0.0f;
        float qq = (t < 8) ? red2[t] : 0.0f;
        #pragma unroll
        for (int o = 4; o > 0; o >>= 1) {
            ss += __shfl_xor_sync(0xffffffffu, ss, o);
            qq += __shfl_xor_sync(0xffffffffu, qq, o);
        }
        if (t == 0) {
            float mu  = ss * (1.0f / DIM);
            float var = qq * (1.0f / DIM) - mu * mu;
            s_mu = mu;
            s_rstd = rsqrtf(var + 1e-5f);
        }
    }
    __syncthreads();
    float mu = s_mu, rstd = s_rstd;
    float4 gg = ((const float4*)gam)[t];
    float4 bb = ((const float4*)bet)[t];
    float o0 = (v.x - mu) * rstd * gg.x + bb.x;
    float o1 = (v.y - mu) * rstd * gg.y + bb.y;
    float o2 = (v.z - mu) * rstd * gg.z + bb.z;
    float o3 = (v.w - mu) * rstd * gg.w + bb.w;
    float* dst = g_xn + (size_t)row * DIM + ((t >> 2) << 4) + (t & 3);
    dst[0]  = f2tf32(o0);
    dst[4]  = f2tf32(o1);
    dst[8]  = f2tf32(o2);
    dst[12] = f2tf32(o3);
}

// ---------------------------------------------------------------------------
// TF32 mma.sync GEMM v4 (NT): BK=16 perm16 tiles, XOR-swizzled 64B rows,
// DOUBLE-BUFFERED cp.async pipeline (2 x 16KB static stages, 32KB total).
// Per iter: issue loads for stage s+1, wait_group 1 (stage s), compute s.
// __launch_bounds__(256,2): 2 CTAs/SM on top of within-CTA overlap.
// which==0: A=g_xn,   B=g_wq, C=g_qkv (K=1024)
// which==1: A=g_attn, B=g_wo, C=Cext  (K=512)
// ---------------------------------------------------------------------------
#define NT_N 1024
#define STG 2048   // floats per stage per operand (128 rows x 16)

__global__ void __launch_bounds__(256, 2) gemm_mma(float* __restrict__ Cext,
                                                   int K, int which) {
    __shared__ float As[2 * STG];
    __shared__ float Bs[2 * STG];

    const float* __restrict__ A = which ? g_attn : g_xn;
    const float* __restrict__ B = which ? g_wo : g_wq;
    float* __restrict__ C       = which ? Cext : g_qkv;

    const int tid  = threadIdx.x;
    const int bn   = blockIdx.x * 128;
    const int bm   = blockIdx.y * 128;
    const int warp = tid >> 5;
    const int lane = tid & 31;
    const int wm   = warp & 3;
    const int wn   = warp >> 2;
    const int r    = lane >> 2;
    const int c    = lane & 3;
    const int lr   = tid >> 1;          // load row 0..127
    const int g0   = (tid & 1) * 2;     // first of 2 groups this thread loads

    float acc[2][8][4];
    #pragma unroll
    for (int mt = 0; mt < 2; mt++)
        #pragma unroll
        for (int nt = 0; nt < 8; nt++)
            #pragma unroll
            for (int q = 0; q < 4; q++) acc[mt][nt][q] = 0.0f;

    // global src base for this thread's two 16B chunks
    const float* ag = A + (size_t)(bm + lr) * K;
    const float* bg = B + (size_t)(bn + lr) * K;
    // swizzled smem dst (group g stored at g ^ (row&3))
    const uint32_t sw0 = (uint32_t)(lr * 16 + ((g0 ^ (lr & 3)) * 4)) * 4u;
    const uint32_t sw1 = (uint32_t)(lr * 16 + (((g0 + 1) ^ (lr & 3)) * 4)) * 4u;
    const uint32_t aBase = cvta_smem(As);
    const uint32_t bBase = cvta_smem(Bs);

    const int NK = K >> 4;

    #define LOAD_STAGE(buf, kt)                                               \
    do {                                                                      \
        uint32_t off = (uint32_t)(buf) * (STG * 4u);                          \
        const float* a0p = ag + (kt) * 16 + g0 * 4;                           \
        const float* b0p = bg + (kt) * 16 + g0 * 4;                           \
        asm volatile("cp.async.cg.shared.global [%0], [%1], 16;"              \
                     :: "r"(aBase + off + sw0), "l"(a0p) : "memory");         \
        asm volatile("cp.async.cg.shared.global [%0], [%1], 16;"              \
                     :: "r"(aBase + off + sw1), "l"(a0p + 4) : "memory");     \
        asm volatile("cp.async.cg.shared.global [%0], [%1], 16;"              \
                     :: "r"(bBase + off + sw0), "l"(b0p) : "memory");         \
        asm volatile("cp.async.cg.shared.global [%0], [%1], 16;"              \
                     :: "r"(bBase + off + sw1), "l"(b0p + 4) : "memory");     \
        asm volatile("cp.async.commit_group;" ::: "memory");                  \
    } while (0)

    LOAD_STAGE(0, 0);

    for (int kt = 0; kt < NK; kt++) {
        if (kt + 1 < NK) {
            LOAD_STAGE((kt + 1) & 1, kt + 1);
            asm volatile("cp.async.wait_group 1;" ::: "memory");
        } else {
            asm volatile("cp.async.wait_group 0;" ::: "memory");
        }
        __syncthreads();

        const float* Ab = As + (kt & 1) * STG;
        const float* Bb = Bs + (kt & 1) * STG;

        // A fragments: one float4 per (mt, low/high row) = k {c,c+4,c+8,c+12}
        float aL4[2][4], aH4[2][4];
        #pragma unroll
        for (int mt = 0; mt < 2; mt++) {
            int rl = wm * 32 + mt * 16 + r;
            *(float4*)aL4[mt] =
                *(const float4*)&Ab[rl * 16 + ((c ^ (rl & 3)) * 4)];
            int rh = rl + 8;      // (rh&3)==(rl&3)
            *(float4*)aH4[mt] =
                *(const float4*)&Bb[0]; // placeholder avoided below
            *(float4*)aH4[mt] =
                *(const float4*)&Ab[rh * 16 + ((c ^ (rh & 3)) * 4)];
        }

        #pragma unroll
        for (int nt = 0; nt < 8; nt++) {
            int nr = wn * 64 + nt * 8 + r;
            float bb4[4];
            *(float4*)bb4 =
                *(const float4*)&Bb[nr * 16 + ((c ^ (nr & 3)) * 4)];
            #pragma unroll
            for (int mt = 0; mt < 2; mt++) {
                // step 0: k = {c, c+4}
                mma_tf32(acc[mt][nt],
                         aL4[mt][0], aH4[mt][0], aL4[mt][1], aH4[mt][1],
                         bb4[0], bb4[1]);
                // step 1: k = {c+8, c+12}
                mma_tf32(acc[mt][nt],
                         aL4[mt][2], aH4[mt][2], aL4[mt][3], aH4[mt][3],
                         bb4[2], bb4[3]);
            }
        }
        __syncthreads();
    }
    #undef LOAD_STAGE

    #pragma unroll
    for (int mt = 0; mt < 2; mt++) {
        #pragma unroll
        for (int nt = 0; nt < 8; nt++) {
            int row = bm + wm * 32 + mt * 16 + r;
            int col = bn + wn * 64 + nt * 8 + 2 * c;
            *(float2*)&C[(size_t)row * NT_N + col] =
                make_float2(acc[mt][nt][0], acc[mt][nt][1]);
            *(float2*)&C[(size_t)(row + 8) * NT_N + col] =
                make_float2(acc[mt][nt][2], acc[mt][nt][3]);
        }
    }
}

// ---------------------------------------------------------------------------
// Tensor-core flash attention (R11 structure; epilogue writes g_attn in
// perm16 layout for the out-projection GEMM).
// ---------------------------------------------------------------------------
struct AttnSmem {
    union {
        struct {
            float ks0[32][36];
            float ks1[32][36];
            float vsT[64][36];
        } kv;
        float qstage[64][68];
    } u;
    float Ss[128 * 36];
    float vstage[32][64];
    float corr[128];
    float lrow[128];
};

__global__ void __launch_bounds__(256) attn_kernel() {
    __shared__ AttnSmem sm;

    const int wi   = blockIdx.x;
    const int bh   = blockIdx.y;
    const int b    = bh >> 3;
    const int h    = bh & 7;
    const int tid  = threadIdx.x;
    const int warp = tid >> 5;
    const int lane = tid & 31;
    const int r    = lane >> 2;
    const int c    = lane & 3;
    const int row0 = warp * 16;

    const float* __restrict__ qkv = g_qkv;

    // ---------------- phase 0: q fragments (rotated, tf32) ----------------
    float qa[8][4];
    #pragma unroll
    for (int half = 0; half < 2; half++) {
        {
            int sr = tid >> 2, quad = tid & 3;
            const float* qg = qkv +
                (size_t)(b * SEQ + wi * WS + half * 64 + sr) * DIM + h * DH;
            #pragma unroll
            for (int p = 0; p < 4; p++)
                *(float4*)&sm.u.qstage[sr][p * 16 + quad * 4] =
                    *(const float4*)(qg + p * 16 + quad * 4);
        }
        __syncthreads();
        #pragma unroll
        for (int p = 0; p < 8; p++) {
            int idx = p * 256 + tid;
            int sr = idx >> 5, e = idx & 31;
            int gi = (half * 64 + sr) * DH;
            float x1 = sm.u.qstage[sr][e], x2 = sm.u.qstage[sr][e + 32];
            float c1 = g_qcs[gi + e],      s1 = g_qsn[gi + e];
            float c2 = g_qcs[gi + e + 32], s2 = g_qsn[gi + e + 32];
            sm.u.qstage[sr][e]      = f2tf32(x1 * c1 - x2 * s1);
            sm.u.qstage[sr][e + 32] = f2tf32(x2 * c2 + x1 * s2);
        }
        __syncthreads();
        if ((warp >> 2) == half) {
            int lr = (warp & 3) * 16 + r;
            #pragma unroll
            for (int kk = 0; kk < 8; kk++) {
                qa[kk][0] = sm.u.qstage[lr][kk * 8 + c];
                qa[kk][1] = sm.u.qstage[lr + 8][kk * 8 + c];
                qa[kk][2] = sm.u.qstage[lr][kk * 8 + c + 4];
                qa[kk][3] = sm.u.qstage[lr + 8][kk * 8 + c + 4];
            }
        }
        __syncthreads();
    }

    float Oacc[8][4];
    #pragma unroll
    for (int nt = 0; nt < 8; nt++)
        #pragma unroll
        for (int q = 0; q < 4; q++) Oacc[nt][q] = 0.0f;

    float m_run = NEG_INF, l_run = 0.0f;

    const uint32_t vstage_base = cvta_smem(&sm.vstage[0][0]);

    // ---------------- chunk loop ----------------
    for (int ch = 0; ch < 12; ch++) {
        int kw = wi - 1 + (ch >> 2);
        if (kw < 0 || kw >= NWIN) continue;

        // (1) prefetch raw v chunk via cp.async
        {
            int j = tid >> 3, u8 = tid & 7;
            const float* vg = qkv +
                (size_t)(b * SEQ + (wi - 1) * WS + ch * 32 + j) * DIM
                + INNER + h * DH + u8 * 8;
            uint32_t dst = vstage_base + (uint32_t)(j * 64 + u8 * 8) * 4u;
            asm volatile("cp.async.cg.shared.global [%0], [%1], 16;"
                         :: "r"(dst), "l"(vg) : "memory");
            asm volatile("cp.async.cg.shared.global [%0], [%1], 16;"
                         :: "r"(dst + 16u), "l"(vg + 4) : "memory");
            asm volatile("cp.async.commit_group;" ::: "memory");
        }

        // (2) k: direct load + fused rotation + permuted store
        #pragma unroll
        for (int p = 0; p < 4; p++) {
            int j = (tid >> 5) + p * 8;
            int e = tid & 31;
            const float* kg = qkv +
                (size_t)(b * SEQ + (wi - 1) * WS + ch * 32 + j) * DIM + h * DH;
            float x1 = kg[e], x2 = kg[e + 32];
            int gi = (ch * 32 + j) * DH;
            sm.u.kv.ks0[j][PERM(e)] =
                f2tf32(x1 * g_kcos[gi + e] - x2 * g_ksin[gi + e]);
            sm.u.kv.ks1[j][PERM(e)] =
                f2tf32(x2 * g_kcos[gi + e + 32] + x1 * g_ksin[gi + e + 32]);
        }
        __syncthreads();   // S1

        // (3) S = Q.K^T
        float Sacc[4][4];
        #pragma unroll
        for (int nt = 0; nt < 4; nt++)
            #pragma unroll
            for (int q = 0; q < 4; q++) Sacc[nt][q] = 0.0f;
        #pragma unroll
        for (int nt = 0; nt < 4; nt++) {
            float bbA[2][4], bbB[2][4];
            int nr = nt * 8 + r;
            *(float4*)bbA[0] = *(const float4*)&sm.u.kv.ks0[nr][c * 8];
            *(float4*)bbA[1] = *(const float4*)&sm.u.kv.ks0[nr][c * 8 + 4];
            *(float4*)bbB[0] = *(const float4*)&sm.u.kv.ks1[nr][c * 8];
            *(float4*)bbB[1] = *(const float4*)&sm.u.kv.ks1[nr][c * 8 + 4];
            #pragma unroll
            for (int s = 0; s < 4; s++) {
                int q = s >> 1, o = (s & 1) * 2;
                mma_tf32(Sacc[nt], qa[s][0], qa[s][1], qa[s][2], qa[s][3],
                         bbA[q][o], bbA[q][o + 1]);
            }
            #pragma unroll
            for (int s = 0; s < 4; s++) {
                int q = s >> 1, o = (s & 1) * 2;
                mma_tf32(Sacc[nt], qa[4 + s][0], qa[4 + s][1],
                         qa[4 + s][2], qa[4 + s][3],
                         bbB[q][o], bbB[q][o + 1]);
            }
        }
        #pragma unroll
        for (int nt = 0; nt < 4; nt++) {
            int j0 = nt * 8 + 2 * c;
            sm.Ss[(row0 + r) * 36 + PERM(j0)]         = Sacc[nt][0];
            sm.Ss[(row0 + r) * 36 + PERM(j0 + 1)]     = Sacc[nt][1];
            sm.Ss[(row0 + r + 8) * 36 + PERM(j0)]     = Sacc[nt][2];
            sm.Ss[(row0 + r + 8) * 36 + PERM(j0 + 1)] = Sacc[nt][3];
        }
        asm volatile("cp.async.wait_group 0;" ::: "memory");
        __syncthreads();   // S2

        // (4a) softmax on threads 0-127
        if (tid < 128) {
            int row = tid;
            int jlo = row - ch * 32;       if (jlo < 0)  jlo = 0;
            int jhi = row + 256 - ch * 32; if (jhi > 31) jhi = 31;
            float cr = 1.0f;
            if (jlo <= jhi) {
                float mc = NEG_INF;
                for (int j = jlo; j <= jhi; j++)
                    mc = fmaxf(mc, sm.Ss[row * 36 + PERM(j)]);
                float mnew = fmaxf(m_run, mc);
                cr = __expf(m_run - mnew);
                float sum = 0.0f;
                #pragma unroll 4
                for (int j = 0; j < 32; j++) {
                    float p = 0.0f;
                    if (j >= jlo && j <= jhi) {
                        p = __expf(sm.Ss[row * 36 + PERM(j)] - mnew);
                        sum += p;
                    }
                    sm.Ss[row * 36 + PERM(j)] = f2tf32(p);
                }
                l_run = l_run * cr + sum;
                m_run = mnew;
            } else {
                #pragma unroll 4
                for (int j = 0; j < 32; j++)
                    sm.Ss[row * 36 + PERM(j)] = 0.0f;
            }
            sm.corr[row] = cr;
        } else {
            // (4b) concurrent v transpose+permute
            int t2 = tid - 128;
            #pragma unroll
            for (int p = 0; p < 16; p++) {
                int idx = p * 128 + t2;
                int j = idx >> 6, e = idx & 63;
                sm.u.kv.vsT[e][PERM(j)] = f2tf32(sm.vstage[j][e]);
            }
        }
        __syncthreads();   // S3

        // (5) O = O*corr + P.V
        float cr0 = sm.corr[row0 + r], cr1 = sm.corr[row0 + r + 8];
        #pragma unroll
        for (int nt = 0; nt < 8; nt++) {
            Oacc[nt][0] *= cr0; Oacc[nt][1] *= cr0;
            Oacc[nt][2] *= cr1; Oacc[nt][3] *= cr1;
        }
        float paL[2][4], paH[2][4];
        *(float4*)paL[0] = *(const float4*)&sm.Ss[(row0 + r) * 36 + c * 8];
        *(float4*)paL[1] = *(const float4*)&sm.Ss[(row0 + r) * 36 + c * 8 + 4];
        *(float4*)paH[0] = *(const float4*)&sm.Ss[(row0 + r + 8) * 36 + c * 8];
        *(float4*)paH[1] = *(const float4*)&sm.Ss[(row0 + r + 8) * 36 + c * 8 + 4];
        #pragma unroll
        for (int nt = 0; nt < 8; nt++) {
            float bb[2][4];
            int nr = nt * 8 + r;
            *(float4*)bb[0] = *(const float4*)&sm.u.kv.vsT[nr][c * 8];
            *(float4*)bb[1] = *(const float4*)&sm.u.kv.vsT[nr][c * 8 + 4];
            #pragma unroll
            for (int s = 0; s < 4; s++) {
                int q = s >> 1, o = (s & 1) * 2;
                mma_tf32(Oacc[nt], paL[q][o], paH[q][o],
                         paL[q][o + 1], paH[q][o + 1],
                         bb[q][o], bb[q][o + 1]);
            }
        }
    }

    // ---------------- finalize: write g_attn tf32-rounded + perm16 --------
    __syncthreads();
    if (tid < 128) sm.lrow[tid] = l_run;
    __syncthreads();
    float inv0 = 1.0f / sm.lrow[row0 + r];
    float inv1 = 1.0f / sm.lrow[row0 + r + 8];
    float* ob = g_attn + (size_t)(b * SEQ + wi * WS) * INNER + h * DH;
    #pragma unroll
    for (int nt = 0; nt < 8; nt++) {
        #pragma unroll
        for (int e = 0; e < 2; e++) {
            int col = nt * 8 + 2 * c + e;   // 0..63 within head
            int slot = GSLOT16(col);
            ob[(size_t)(row0 + r) * INNER + slot] =
                f2tf32(Oacc[nt][e] * inv0);
            ob[(size_t)(row0 + r + 8) * INNER + slot] =
                f2tf32(Oacc[nt][2 + e] * inv1);
        }
    }
}

// ---------------------------------------------------------------------------
// Launch: pure kernel launches, zero runtime API calls.
// ---------------------------------------------------------------------------
extern "C" void kernel_launch(void* const* d_in, const int* in_sizes, int n_in,
                              void* d_out, int out_size) {
    const float* x     = (const float*)d_in[0];
    const float* ln_g  = (const float*)d_in[1];
    const float* ln_b  = (const float*)d_in[2];
    const float* w_qkv = (const float*)d_in[3];
    const float* w_out = (const float*)d_in[4];
    float* out = (float*)d_out;

    rope_precompute_kernel<<<(JLEN * DH + 255) / 256, 256>>>();
    wperm_kernel<<<(DIM * DIM + 255) / 256, 256>>>(w_qkv, w_out);
    ln_kernel<<<M_ROWS, 256>>>(x, ln_g, ln_b);

    // qkv = xn @ w_qkv^T  (K=1024)
    gemm_mma<<<dim3(NT_N / 128, M_ROWS / 128), 256>>>(nullptr, DIM, 0);

    attn_kernel<<<dim3(NWIN, BATCH * HEADS), 256>>>();

    // out = attn @ w_out^T (K=512)
    gemm_mma<<<dim3(NT_N / 128, M_ROWS / 128), 256>>>(out, INNER, 1);
}

// round 13
// speedup vs baseline: 1.2473x; 1.0056x over previous
#include <cuda_runtime.h>
#include <cuda_bf16.h>
#include <math.h>
#include <stdint.h>

// ---------------------------------------------------------------------------
// Problem constants
// ---------------------------------------------------------------------------
#define BATCH 4
#define SEQ   4096
#define DIM   1024
#define HEADS 8
#define DH    64
#define WS    128
#define NWIN  32
#define INNER 512
#define JLEN  384
#define M_ROWS (BATCH * SEQ)   // 16384

#define NEG_INF (-3.402823466e+38f)

// ---------------------------------------------------------------------------
// Scratch. g_xn / g_attn / g_wq / g_wo hold tf32-rounded data in perm16
// layout: within each 16-k tile, element k lives at slot (k&3)*4+((k>>2)&3).
// ---------------------------------------------------------------------------
__device__ float g_xn  [M_ROWS * DIM];
__device__ float g_qkv [M_ROWS * DIM];      // normal layout (attn reads it)
__device__ float g_attn[M_ROWS * INNER];
__device__ float g_wq  [DIM * DIM];
__device__ float g_wo  [DIM * INNER];
__device__ float g_kcos[JLEN * DH];
__device__ float g_ksin[JLEN * DH];
__device__ float g_qcs [WS * DH];
__device__ float g_qsn [WS * DH];

// ---------------------------------------------------------------------------
// Helpers
// ---------------------------------------------------------------------------
__device__ __forceinline__ float f2tf32(float x) {
    uint32_t y;
    asm("cvt.rna.tf32.f32 %0, %1;" : "=r"(y) : "f"(x));
    return __uint_as_float(y);
}

__device__ __forceinline__ void mma_tf32(float* d,
                                         float a0, float a1,
                                         float a2, float a3,
                                         float b0, float b1) {
    asm volatile(
        "mma.sync.aligned.m16n8k8.row.col.f32.tf32.tf32.f32 "
        "{%0,%1,%2,%3}, {%4,%5,%6,%7}, {%8,%9}, {%0,%1,%2,%3};\n"
        : "+f"(d[0]), "+f"(d[1]), "+f"(d[2]), "+f"(d[3])
        : "r"(__float_as_uint(a0)), "r"(__float_as_uint(a1)),
          "r"(__float_as_uint(a2)), "r"(__float_as_uint(a3)),
          "r"(__float_as_uint(b0)), "r"(__float_as_uint(b1)));
}

__device__ __forceinline__ uint32_t cvta_smem(const void* p) {
    uint32_t a;
    asm("{ .reg .u64 t; cvta.to.shared.u64 t, %1; cvt.u32.u64 %0, t; }"
        : "=r"(a) : "l"(p));
    return a;
}

#define PERM(j)    (((j) & 3) * 8 + ((j) >> 2))                 // 32-k (attn)
#define GSLOT16(k) ((((k) >> 4) << 4) + (((k) & 3) << 2) + (((k) >> 2) & 3))

// ---------------------------------------------------------------------------
// Rotary / xpos coefficient precompute
// ---------------------------------------------------------------------------
__global__ void rope_precompute_kernel() {
    int idx = blockIdx.x * blockDim.x + threadIdx.x;
    if (idx >= JLEN * DH) return;
    int t = idx / DH;
    int e = idx % DH;
    int f = e & 31;
    float invf = powf(10000.0f, -(2.0f * (float)f) / (float)DH);
    float ang  = (float)t * invf;
    float sb   = (2.0f * (float)f + 0.4f * (float)DH) / (1.4f * (float)DH);
    float pw   = ((float)t - (float)(JLEN / 2)) / (float)(WS / 2);
    float sc   = powf(sb, pw);
    float c = cosf(ang), s = sinf(ang);
    g_kcos[idx] = c / sc;
    g_ksin[idx] = s / sc;
    if (t >= JLEN - WS) {
        int i = t - (JLEN - WS);
        g_qcs[i * DH + e] = c * sc * 0.125f;
        g_qsn[i * DH + e] = s * sc * 0.125f;
    }
}

// ---------------------------------------------------------------------------
// Weight pre-permute + tf32 round (one-off)
// ---------------------------------------------------------------------------
__global__ void wperm_kernel(const float* __restrict__ w_qkv,
                             const float* __restrict__ w_out) {
    int idx = blockIdx.x * blockDim.x + threadIdx.x;
    if (idx < DIM * DIM) {
        int row = idx >> 10, k = idx & 1023;
        g_wq[(size_t)row * DIM + GSLOT16(k)] = f2tf32(w_qkv[idx]);
    }
    if (idx < DIM * INNER) {
        int row = idx / INNER, k = idx % INNER;
        g_wo[(size_t)row * INNER + GSLOT16(k)] = f2tf32(w_out[idx]);
    }
}

// ---------------------------------------------------------------------------
// LayerNorm -> g_xn (tf32-rounded, perm16)
// k = 4t+j -> tile t>>2, slot j*4 + (t&3)
// ---------------------------------------------------------------------------
__global__ void __launch_bounds__(256) ln_kernel(const float* __restrict__ x,
                                                 const float* __restrict__ gam,
                                                 const float* __restrict__ bet) {
    __shared__ float red [8];
    __shared__ float red2[8];
    __shared__ float s_mu, s_rstd;
    int row = blockIdx.x;
    int t = threadIdx.x;
    float4 v = ((const float4*)(x + (size_t)row * DIM))[t];
    float s  = v.x + v.y + v.z + v.w;
    float sq = v.x * v.x + v.y * v.y + v.z * v.z + v.w * v.w;
    #pragma unroll
    for (int o = 16; o > 0; o >>= 1) {
        s  += __shfl_xor_sync(0xffffffffu, s,  o);
        sq += __shfl_xor_sync(0xffffffffu, sq, o);
    }
    if ((t & 31) == 0) { red[t >> 5] = s; red2[t >> 5] = sq; }
    __syncthreads();
    if (t < 32) {
        float ss = (t < 8) ? red [t] : 0.0f;
        float qq = (t < 8) ? red2[t] : 0.0f;
        #pragma unroll
        for (int o = 4; o > 0; o >>= 1) {
            ss += __shfl_xor_sync(0xffffffffu, ss, o);
            qq += __shfl_xor_sync(0xffffffffu, qq, o);
        }
        if (t == 0) {
            float mu  = ss * (1.0f / DIM);
            float var = qq * (1.0f / DIM) - mu * mu;
            s_mu = mu;
            s_rstd = rsqrtf(var + 1e-5f);
        }
    }
    __syncthreads();
    float mu = s_mu, rstd = s_rstd;
    float4 gg = ((const float4*)gam)[t];
    float4 bb = ((const float4*)bet)[t];
    float o0 = (v.x - mu) * rstd * gg.x + bb.x;
    float o1 = (v.y - mu) * rstd * gg.y + bb.y;
    float o2 = (v.z - mu) * rstd * gg.z + bb.z;
    float o3 = (v.w - mu) * rstd * gg.w + bb.w;
    float* dst = g_xn + (size_t)row * DIM + ((t >> 2) << 4) + (t & 3);
    dst[0]  = f2tf32(o0);
    dst[4]  = f2tf32(o1);
    dst[8]  = f2tf32(o2);
    dst[12] = f2tf32(o3);
}

// ---------------------------------------------------------------------------
// TF32 mma.sync GEMM v5 (NT): BK=16 perm16 tiles, XOR-swizzled 64B rows,
// THREE-STAGE cp.async pipeline (3 x 16KB = 48KB static), ONE sync per iter.
// Hazard analysis: LOAD(kt+2) writes buf (kt+2)%3 == (kt-1)%3, whose readers
// (compute(kt-1)) all precede the iter-kt sync in program order; the load is
// issued after that sync -> safe with a single barrier.
// Tail: wait_group 1 while kt+1<NK (2 groups pending -> stage kt drained);
// wait_group 0 on the last iter (only 1 pending; wait_group 1 would NOT wait).
// which==0: A=g_xn,   B=g_wq, C=g_qkv (K=1024)
// which==1: A=g_attn, B=g_wo, C=Cext  (K=512)
// ---------------------------------------------------------------------------
#define NT_N 1024
#define STG 2048   // floats per stage per operand (128 rows x 16)

__global__ void __launch_bounds__(256, 2) gemm_mma(float* __restrict__ Cext,
                                                   int K, int which) {
    __shared__ float As[3 * STG];   // 24 KB
    __shared__ float Bs[3 * STG];   // 24 KB

    const float* __restrict__ A = which ? g_attn : g_xn;
    const float* __restrict__ B = which ? g_wo : g_wq;
    float* __restrict__ C       = which ? Cext : g_qkv;

    const int tid  = threadIdx.x;
    const int bn   = blockIdx.x * 128;
    const int bm   = blockIdx.y * 128;
    const int warp = tid >> 5;
    const int lane = tid & 31;
    const int wm   = warp & 3;
    const int wn   = warp >> 2;
    const int r    = lane >> 2;
    const int c    = lane & 3;
    const int lr   = tid >> 1;          // load row 0..127
    const int g0   = (tid & 1) * 2;     // first of 2 groups this thread loads

    float acc[2][8][4];
    #pragma unroll
    for (int mt = 0; mt < 2; mt++)
        #pragma unroll
        for (int nt = 0; nt < 8; nt++)
            #pragma unroll
            for (int q = 0; q < 4; q++) acc[mt][nt][q] = 0.0f;

    const float* ag = A + (size_t)(bm + lr) * K;
    const float* bg = B + (size_t)(bn + lr) * K;
    const uint32_t sw0 = (uint32_t)(lr * 16 + ((g0 ^ (lr & 3)) * 4)) * 4u;
    const uint32_t sw1 = (uint32_t)(lr * 16 + (((g0 + 1) ^ (lr & 3)) * 4)) * 4u;
    const uint32_t aBase = cvta_smem(As);
    const uint32_t bBase = cvta_smem(Bs);

    const int NK = K >> 4;

    #define LOAD_STAGE(buf, kt)                                               \
    do {                                                                      \
        uint32_t off = (uint32_t)(buf) * (STG * 4u);                          \
        const float* a0p = ag + (kt) * 16 + g0 * 4;                           \
        const float* b0p = bg + (kt) * 16 + g0 * 4;                           \
        asm volatile("cp.async.cg.shared.global [%0], [%1], 16;"              \
                     :: "r"(aBase + off + sw0), "l"(a0p) : "memory");         \
        asm volatile("cp.async.cg.shared.global [%0], [%1], 16;"              \
                     :: "r"(aBase + off + sw1), "l"(a0p + 4) : "memory");     \
        asm volatile("cp.async.cg.shared.global [%0], [%1], 16;"              \
                     :: "r"(bBase + off + sw0), "l"(b0p) : "memory");         \
        asm volatile("cp.async.cg.shared.global [%0], [%1], 16;"              \
                     :: "r"(bBase + off + sw1), "l"(b0p + 4) : "memory");     \
        asm volatile("cp.async.commit_group;" ::: "memory");                  \
    } while (0)

    LOAD_STAGE(0, 0);
    LOAD_STAGE(1, 1);                    // NK >= 32 always

    int cur = 0;                         // buffer of stage kt
    int lb  = 2;                         // buffer for stage kt+2

    for (int kt = 0; kt < NK; kt++) {
        if (kt + 1 < NK) {
            asm volatile("cp.async.wait_group 1;" ::: "memory");
        } else {
            asm volatile("cp.async.wait_group 0;" ::: "memory");
        }
        __syncthreads();

        if (kt + 2 < NK) LOAD_STAGE(lb, kt + 2);

        const float* Ab = As + cur * STG;
        const float* Bb = Bs + cur * STG;

        // A fragments: one float4 per (mt, low/high row) = k {c,c+4,c+8,c+12}
        float aL4[2][4], aH4[2][4];
        #pragma unroll
        for (int mt = 0; mt < 2; mt++) {
            int rl = wm * 32 + mt * 16 + r;
            *(float4*)aL4[mt] =
                *(const float4*)&Ab[rl * 16 + ((c ^ (rl & 3)) * 4)];
            int rh = rl + 8;      // (rh&3)==(rl&3)
            *(float4*)aH4[mt] =
                *(const float4*)&Ab[rh * 16 + ((c ^ (rh & 3)) * 4)];
        }

        #pragma unroll
        for (int nt = 0; nt < 8; nt++) {
            int nr = wn * 64 + nt * 8 + r;
            float bb4[4];
            *(float4*)bb4 =
                *(const float4*)&Bb[nr * 16 + ((c ^ (nr & 3)) * 4)];
            #pragma unroll
            for (int mt = 0; mt < 2; mt++) {
                // step 0: k = {c, c+4}
                mma_tf32(acc[mt][nt],
                         aL4[mt][0], aH4[mt][0], aL4[mt][1], aH4[mt][1],
                         bb4[0], bb4[1]);
                // step 1: k = {c+8, c+12}
                mma_tf32(acc[mt][nt],
                         aL4[mt][2], aH4[mt][2], aL4[mt][3], aH4[mt][3],
                         bb4[2], bb4[3]);
            }
        }

        cur = (cur == 2) ? 0 : cur + 1;
        lb  = (lb  == 2) ? 0 : lb  + 1;
    }
    #undef LOAD_STAGE

    #pragma unroll
    for (int mt = 0; mt < 2; mt++) {
        #pragma unroll
        for (int nt = 0; nt < 8; nt++) {
            int row = bm + wm * 32 + mt * 16 + r;
            int col = bn + wn * 64 + nt * 8 + 2 * c;
            *(float2*)&C[(size_t)row * NT_N + col] =
                make_float2(acc[mt][nt][0], acc[mt][nt][1]);
            *(float2*)&C[(size_t)(row + 8) * NT_N + col] =
                make_float2(acc[mt][nt][2], acc[mt][nt][3]);
        }
    }
}

// ---------------------------------------------------------------------------
// Tensor-core flash attention (unchanged from R12; epilogue writes g_attn in
// perm16 layout for the out-projection GEMM).
// ---------------------------------------------------------------------------
struct AttnSmem {
    union {
        struct {
            float ks0[32][36];
            float ks1[32][36];
            float vsT[64][36];
        } kv;
        float qstage[64][68];
    } u;
    float Ss[128 * 36];
    float vstage[32][64];
    float corr[128];
    float lrow[128];
};

__global__ void __launch_bounds__(256) attn_kernel() {
    __shared__ AttnSmem sm;

    const int wi   = blockIdx.x;
    const int bh   = blockIdx.y;
    const int b    = bh >> 3;
    const int h    = bh & 7;
    const int tid  = threadIdx.x;
    const int warp = tid >> 5;
    const int lane = tid & 31;
    const int r    = lane >> 2;
    const int c    = lane & 3;
    const int row0 = warp * 16;

    const float* __restrict__ qkv = g_qkv;

    // ---------------- phase 0: q fragments (rotated, tf32) ----------------
    float qa[8][4];
    #pragma unroll
    for (int half = 0; half < 2; half++) {
        {
            int sr = tid >> 2, quad = tid & 3;
            const float* qg = qkv +
                (size_t)(b * SEQ + wi * WS + half * 64 + sr) * DIM + h * DH;
            #pragma unroll
            for (int p = 0; p < 4; p++)
                *(float4*)&sm.u.qstage[sr][p * 16 + quad * 4] =
                    *(const float4*)(qg + p * 16 + quad * 4);
        }
        __syncthreads();
        #pragma unroll
        for (int p = 0; p < 8; p++) {
            int idx = p * 256 + tid;
            int sr = idx >> 5, e = idx & 31;
            int gi = (half * 64 + sr) * DH;
            float x1 = sm.u.qstage[sr][e], x2 = sm.u.qstage[sr][e + 32];
            float c1 = g_qcs[gi + e],      s1 = g_qsn[gi + e];
            float c2 = g_qcs[gi + e + 32], s2 = g_qsn[gi + e + 32];
            sm.u.qstage[sr][e]      = f2tf32(x1 * c1 - x2 * s1);
            sm.u.qstage[sr][e + 32] = f2tf32(x2 * c2 + x1 * s2);
        }
        __syncthreads();
        if ((warp >> 2) == half) {
            int lr = (warp & 3) * 16 + r;
            #pragma unroll
            for (int kk = 0; kk < 8; kk++) {
                qa[kk][0] = sm.u.qstage[lr][kk * 8 + c];
                qa[kk][1] = sm.u.qstage[lr + 8][kk * 8 + c];
                qa[kk][2] = sm.u.qstage[lr][kk * 8 + c + 4];
                qa[kk][3] = sm.u.qstage[lr + 8][kk * 8 + c + 4];
            }
        }
        __syncthreads();
    }

    float Oacc[8][4];
    #pragma unroll
    for (int nt = 0; nt < 8; nt++)
        #pragma unroll
        for (int q = 0; q < 4; q++) Oacc[nt][q] = 0.0f;

    float m_run = NEG_INF, l_run = 0.0f;

    const uint32_t vstage_base = cvta_smem(&sm.vstage[0][0]);

    // ---------------- chunk loop ----------------
    for (int ch = 0; ch < 12; ch++) {
        int kw = wi - 1 + (ch >> 2);
        if (kw < 0 || kw >= NWIN) continue;

        // (1) prefetch raw v chunk via cp.async
        {
            int j = tid >> 3, u8 = tid & 7;
            const float* vg = qkv +
                (size_t)(b * SEQ + (wi - 1) * WS + ch * 32 + j) * DIM
                + INNER + h * DH + u8 * 8;
            uint32_t dst = vstage_base + (uint32_t)(j * 64 + u8 * 8) * 4u;
            asm volatile("cp.async.cg.shared.global [%0], [%1], 16;"
                         :: "r"(dst), "l"(vg) : "memory");
            asm volatile("cp.async.cg.shared.global [%0], [%1], 16;"
                         :: "r"(dst + 16u), "l"(vg + 4) : "memory");
            asm volatile("cp.async.commit_group;" ::: "memory");
        }

        // (2) k: direct load + fused rotation + permuted store
        #pragma unroll
        for (int p = 0; p < 4; p++) {
            int j = (tid >> 5) + p * 8;
            int e = tid & 31;
            const float* kg = qkv +
                (size_t)(b * SEQ + (wi - 1) * WS + ch * 32 + j) * DIM + h * DH;
            float x1 = kg[e], x2 = kg[e + 32];
            int gi = (ch * 32 + j) * DH;
            sm.u.kv.ks0[j][PERM(e)] =
                f2tf32(x1 * g_kcos[gi + e] - x2 * g_ksin[gi + e]);
            sm.u.kv.ks1[j][PERM(e)] =
                f2tf32(x2 * g_kcos[gi + e + 32] + x1 * g_ksin[gi + e + 32]);
        }
        __syncthreads();   // S1

        // (3) S = Q.K^T
        float Sacc[4][4];
        #pragma unroll
        for (int nt = 0; nt < 4; nt++)
            #pragma unroll
            for (int q = 0; q < 4; q++) Sacc[nt][q] = 0.0f;
        #pragma unroll
        for (int nt = 0; nt < 4; nt++) {
            float bbA[2][4], bbB[2][4];
            int nr = nt * 8 + r;
            *(float4*)bbA[0] = *(const float4*)&sm.u.kv.ks0[nr][c * 8];
            *(float4*)bbA[1] = *(const float4*)&sm.u.kv.ks0[nr][c * 8 + 4];
            *(float4*)bbB[0] = *(const float4*)&sm.u.kv.ks1[nr][c * 8];
            *(float4*)bbB[1] = *(const float4*)&sm.u.kv.ks1[nr][c * 8 + 4];
            #pragma unroll
            for (int s = 0; s < 4; s++) {
                int q = s >> 1, o = (s & 1) * 2;
                mma_tf32(Sacc[nt], qa[s][0], qa[s][1], qa[s][2], qa[s][3],
                         bbA[q][o], bbA[q][o + 1]);
            }
            #pragma unroll
            for (int s = 0; s < 4; s++) {
                int q = s >> 1, o = (s & 1) * 2;
                mma_tf32(Sacc[nt], qa[4 + s][0], qa[4 + s][1],
                         qa[4 + s][2], qa[4 + s][3],
                         bbB[q][o], bbB[q][o + 1]);
            }
        }
        #pragma unroll
        for (int nt = 0; nt < 4; nt++) {
            int j0 = nt * 8 + 2 * c;
            sm.Ss[(row0 + r) * 36 + PERM(j0)]         = Sacc[nt][0];
            sm.Ss[(row0 + r) * 36 + PERM(j0 + 1)]     = Sacc[nt][1];
            sm.Ss[(row0 + r + 8) * 36 + PERM(j0)]     = Sacc[nt][2];
            sm.Ss[(row0 + r + 8) * 36 + PERM(j0 + 1)] = Sacc[nt][3];
        }
        asm volatile("cp.async.wait_group 0;" ::: "memory");
        __syncthreads();   // S2

        // (4a) softmax on threads 0-127
        if (tid < 128) {
            int row = tid;
            int jlo = row - ch * 32;       if (jlo < 0)  jlo = 0;
            int jhi = row + 256 - ch * 32; if (jhi > 31) jhi = 31;
            float cr = 1.0f;
            if (jlo <= jhi) {
                float mc = NEG_INF;
                for (int j = jlo; j <= jhi; j++)
                    mc = fmaxf(mc, sm.Ss[row * 36 + PERM(j)]);
                float mnew = fmaxf(m_run, mc);
                cr = __expf(m_run - mnew);
                float sum = 0.0f;
                #pragma unroll 4
                for (int j = 0; j < 32; j++) {
                    float p = 0.0f;
                    if (j >= jlo && j <= jhi) {
                        p = __expf(sm.Ss[row * 36 + PERM(j)] - mnew);
                        sum += p;
                    }
                    sm.Ss[row * 36 + PERM(j)] = f2tf32(p);
                }
                l_run = l_run * cr + sum;
                m_run = mnew;
            } else {
                #pragma unroll 4
                for (int j = 0; j < 32; j++)
                    sm.Ss[row * 36 + PERM(j)] = 0.0f;
            }
            sm.corr[row] = cr;
        } else {
            // (4b) concurrent v transpose+permute
            int t2 = tid - 128;
            #pragma unroll
            for (int p = 0; p < 16; p++) {
                int idx = p * 128 + t2;
                int j = idx >> 6, e = idx & 63;
                sm.u.kv.vsT[e][PERM(j)] = f2tf32(sm.vstage[j][e]);
            }
        }
        __syncthreads();   // S3

        // (5) O = O*corr + P.V
        float cr0 = sm.corr[row0 + r], cr1 = sm.corr[row0 + r + 8];
        #pragma unroll
        for (int nt = 0; nt < 8; nt++) {
            Oacc[nt][0] *= cr0; Oacc[nt][1] *= cr0;
            Oacc[nt][2] *= cr1; Oacc[nt][3] *= cr1;
        }
        float paL[2][4], paH[2][4];
        *(float4*)paL[0] = *(const float4*)&sm.Ss[(row0 + r) * 36 + c * 8];
        *(float4*)paL[1] = *(const float4*)&sm.Ss[(row0 + r) * 36 + c * 8 + 4];
        *(float4*)paH[0] = *(const float4*)&sm.Ss[(row0 + r + 8) * 36 + c * 8];
        *(float4*)paH[1] = *(const float4*)&sm.Ss[(row0 + r + 8) * 36 + c * 8 + 4];
        #pragma unroll
        for (int nt = 0; nt < 8; nt++) {
            float bb[2][4];
            int nr = nt * 8 + r;
            *(float4*)bb[0] = *(const float4*)&sm.u.kv.vsT[nr][c * 8];
            *(float4*)bb[1] = *(const float4*)&sm.u.kv.vsT[nr][c * 8 + 4];
            #pragma unroll
            for (int s = 0; s < 4; s++) {
                int q = s >> 1, o = (s & 1) * 2;
                mma_tf32(Oacc[nt], paL[q][o], paH[q][o],
                         paL[q][o + 1], paH[q][o + 1],
                         bb[q][o], bb[q][o + 1]);
            }
        }
    }

    // ---------------- finalize: write g_attn tf32-rounded + perm16 --------
    __syncthreads();
    if (tid < 128) sm.lrow[tid] = l_run;
    __syncthreads();
    float inv0 = 1.0f / sm.lrow[row0 + r];
    float inv1 = 1.0f / sm.lrow[row0 + r + 8];
    float* ob = g_attn + (size_t)(b * SEQ + wi * WS) * INNER + h * DH;
    #pragma unroll
    for (int nt = 0; nt < 8; nt++) {
        #pragma unroll
        for (int e = 0; e < 2; e++) {
            int col = nt * 8 + 2 * c + e;   // 0..63 within head
            int slot = GSLOT16(col);
            ob[(size_t)(row0 + r) * INNER + slot] =
                f2tf32(Oacc[nt][e] * inv0);
            ob[(size_t)(row0 + r + 8) * INNER + slot] =
                f2tf32(Oacc[nt][2 + e] * inv1);
        }
    }
}

// ---------------------------------------------------------------------------
// Launch: pure kernel launches, zero runtime API calls.
// ---------------------------------------------------------------------------
extern "C" void kernel_launch(void* const* d_in, const int* in_sizes, int n_in,
                              void* d_out, int out_size) {
    const float* x     = (const float*)d_in[0];
    const float* ln_g  = (const float*)d_in[1];
    const float* ln_b  = (const float*)d_in[2];
    const float* w_qkv = (const float*)d_in[3];
    const float* w_out = (const float*)d_in[4];
    float* out = (float*)d_out;

    rope_precompute_kernel<<<(JLEN * DH + 255) / 256, 256>>>();
    wperm_kernel<<<(DIM * DIM + 255) / 256, 256>>>(w_qkv, w_out);
    ln_kernel<<<M_ROWS, 256>>>(x, ln_g, ln_b);

    // qkv = xn @ w_qkv^T  (K=1024)
    gemm_mma<<<dim3(NT_N / 128, M_ROWS / 128), 256>>>(nullptr, DIM, 0);

    attn_kernel<<<dim3(NWIN, BATCH * HEADS), 256>>>();

    // out = attn @ w_out^T (K=512)
    gemm_mma<<<dim3(NT_N / 128, M_ROWS / 128), 256>>>(out, INNER, 1);
}

// round 16
// speedup vs baseline: 1.4887x; 1.1935x over previous
#include <cuda_runtime.h>
#include <cuda_bf16.h>
#include <math.h>
#include <stdint.h>

// ---------------------------------------------------------------------------
// Problem constants
// ---------------------------------------------------------------------------
#define BATCH 4
#define SEQ   4096
#define DIM   1024
#define HEADS 8
#define DH    64
#define WS    128
#define NWIN  32
#define INNER 512
#define JLEN  384
#define M_ROWS (BATCH * SEQ)   // 16384

#define NEG_INF (-3.402823466e+38f)

// ---------------------------------------------------------------------------
// Scratch. g_xn / g_attn / g_wq / g_wo hold tf32-rounded data in perm16
// layout: within each 16-k tile, element k lives at slot (k&3)*4+((k>>2)&3).
// ---------------------------------------------------------------------------
__device__ float g_xn  [M_ROWS * DIM];
__device__ float g_qkv [M_ROWS * DIM];      // normal layout (attn reads it)
__device__ float g_attn[M_ROWS * INNER];
__device__ float g_wq  [DIM * DIM];
__device__ float g_wo  [DIM * INNER];
__device__ float g_kcos[JLEN * DH];
__device__ float g_ksin[JLEN * DH];
__device__ float g_qcs [WS * DH];
__device__ float g_qsn [WS * DH];

// ---------------------------------------------------------------------------
// Helpers
// ---------------------------------------------------------------------------
__device__ __forceinline__ float f2tf32(float x) {
    uint32_t y;
    asm("cvt.rna.tf32.f32 %0, %1;" : "=r"(y) : "f"(x));
    return __uint_as_float(y);
}

__device__ __forceinline__ void mma_tf32(float* d,
                                         float a0, float a1,
                                         float a2, float a3,
                                         float b0, float b1) {
    asm volatile(
        "mma.sync.aligned.m16n8k8.row.col.f32.tf32.tf32.f32 "
        "{%0,%1,%2,%3}, {%4,%5,%6,%7}, {%8,%9}, {%0,%1,%2,%3};\n"
        : "+f"(d[0]), "+f"(d[1]), "+f"(d[2]), "+f"(d[3])
        : "r"(__float_as_uint(a0)), "r"(__float_as_uint(a1)),
          "r"(__float_as_uint(a2)), "r"(__float_as_uint(a3)),
          "r"(__float_as_uint(b0)), "r"(__float_as_uint(b1)));
}

__device__ __forceinline__ uint32_t cvta_smem(const void* p) {
    uint32_t a;
    asm("{ .reg .u64 t; cvta.to.shared.u64 t, %1; cvt.u32.u64 %0, t; }"
        : "=r"(a) : "l"(p));
    return a;
}

#define PERM(j)    (((j) & 3) * 8 + ((j) >> 2))                 // 32-k (attn)
#define GSLOT16(k) ((((k) >> 4) << 4) + (((k) & 3) << 2) + (((k) >> 2) & 3))

// ---------------------------------------------------------------------------
// Rotary / xpos coefficient precompute
// ---------------------------------------------------------------------------
__global__ void rope_precompute_kernel() {
    int idx = blockIdx.x * blockDim.x + threadIdx.x;
    if (idx >= JLEN * DH) return;
    int t = idx / DH;
    int e = idx % DH;
    int f = e & 31;
    float invf = powf(10000.0f, -(2.0f * (float)f) / (float)DH);
    float ang  = (float)t * invf;
    float sb   = (2.0f * (float)f + 0.4f * (float)DH) / (1.4f * (float)DH);
    float pw   = ((float)t - (float)(JLEN / 2)) / (float)(WS / 2);
    float sc   = powf(sb, pw);
    float c = cosf(ang), s = sinf(ang);
    g_kcos[idx] = c / sc;
    g_ksin[idx] = s / sc;
    if (t >= JLEN - WS) {
        int i = t - (JLEN - WS);
        g_qcs[i * DH + e] = c * sc * 0.125f;
        g_qsn[i * DH + e] = s * sc * 0.125f;
    }
}

// ---------------------------------------------------------------------------
// Weight pre-permute + tf32 round (one-off)
// ---------------------------------------------------------------------------
__global__ void wperm_kernel(const float* __restrict__ w_qkv,
                             const float* __restrict__ w_out) {
    int idx = blockIdx.x * blockDim.x + threadIdx.x;
    if (idx < DIM * DIM) {
        int row = idx >> 10, k = idx & 1023;
        g_wq[(size_t)row * DIM + GSLOT16(k)] = f2tf32(w_qkv[idx]);
    }
    if (idx < DIM * INNER) {
        int row = idx / INNER, k = idx % INNER;
        g_wo[(size_t)row * INNER + GSLOT16(k)] = f2tf32(w_out[idx]);
    }
}

// ---------------------------------------------------------------------------
// LayerNorm -> g_xn (tf32-rounded, perm16)
// ---------------------------------------------------------------------------
__global__ void __launch_bounds__(256) ln_kernel(const float* __restrict__ x,
                                                 const float* __restrict__ gam,
                                                 const float* __restrict__ bet) {
    __shared__ float red [8];
    __shared__ float red2[8];
    __shared__ float s_mu, s_rstd;
    int row = blockIdx.x;
    int t = threadIdx.x;
    float4 v = ((const float4*)(x + (size_t)row * DIM))[t];
    float s  = v.x + v.y + v.z + v.w;
    float sq = v.x * v.x + v.y * v.y + v.z * v.z + v.w * v.w;
    #pragma unroll
    for (int o = 16; o > 0; o >>= 1) {
        s  += __shfl_xor_sync(0xffffffffu, s,  o);
        sq += __shfl_xor_sync(0xffffffffu, sq, o);
    }
    if ((t & 31) == 0) { red[t >> 5] = s; red2[t >> 5] = sq; }
    __syncthreads();
    if (t < 32) {
        float ss = (t < 8) ? red [t] : 0.0f;
        float qq = (t < 8) ? red2[t] : 0.0f;
        #pragma unroll
        for (int o = 4; o > 0; o >>= 1) {
            ss += __shfl_xor_sync(0xffffffffu, ss, o);
            qq += __shfl_xor_sync(0xffffffffu, qq, o);
        }
        if (t == 0) {
            float mu  = ss * (1.0f / DIM);
            float var = qq * (1.0f / DIM) - mu * mu;
            s_mu = mu;
            s_rstd = rsqrtf(var + 1e-5f);
        }
    }
    __syncthreads();
    float mu = s_mu, rstd = s_rstd;
    float4 gg = ((const float4*)gam)[t];
    float4 bb = ((const float4*)bet)[t];
    float o0 = (v.x - mu) * rstd * gg.x + bb.x;
    float o1 = (v.y - mu) * rstd * gg.y + bb.y;
    float o2 = (v.z - mu) * rstd * gg.z + bb.z;
    float o3 = (v.w - mu) * rstd * gg.w + bb.w;
    float* dst = g_xn + (size_t)row * DIM + ((t >> 2) << 4) + (t & 3);
    dst[0]  = f2tf32(o0);
    dst[4]  = f2tf32(o1);
    dst[8]  = f2tf32(o2);
    dst[12] = f2tf32(o3);
}

// ---------------------------------------------------------------------------
// TF32 mma.sync GEMM v5 (unchanged from R13 best).
// ---------------------------------------------------------------------------
#define NT_N 1024
#define STG 2048

__global__ void __launch_bounds__(256, 2) gemm_mma(float* __restrict__ Cext,
                                                   int K, int which) {
    __shared__ float As[3 * STG];
    __shared__ float Bs[3 * STG];

    const float* __restrict__ A = which ? g_attn : g_xn;
    const float* __restrict__ B = which ? g_wo : g_wq;
    float* __restrict__ C       = which ? Cext : g_qkv;

    const int tid  = threadIdx.x;
    const int bn   = blockIdx.x * 128;
    const int bm   = blockIdx.y * 128;
    const int warp = tid >> 5;
    const int lane = tid & 31;
    const int wm   = warp & 3;
    const int wn   = warp >> 2;
    const int r    = lane >> 2;
    const int c    = lane & 3;
    const int lr   = tid >> 1;
    const int g0   = (tid & 1) * 2;

    float acc[2][8][4];
    #pragma unroll
    for (int mt = 0; mt < 2; mt++)
        #pragma unroll
        for (int nt = 0; nt < 8; nt++)
            #pragma unroll
            for (int q = 0; q < 4; q++) acc[mt][nt][q] = 0.0f;

    const float* ag = A + (size_t)(bm + lr) * K;
    const float* bg = B + (size_t)(bn + lr) * K;
    const uint32_t sw0 = (uint32_t)(lr * 16 + ((g0 ^ (lr & 3)) * 4)) * 4u;
    const uint32_t sw1 = (uint32_t)(lr * 16 + (((g0 + 1) ^ (lr & 3)) * 4)) * 4u;
    const uint32_t aBase = cvta_smem(As);
    const uint32_t bBase = cvta_smem(Bs);

    const int NK = K >> 4;

    #define LOAD_STAGE(buf, kt)                                               \
    do {                                                                      \
        uint32_t off = (uint32_t)(buf) * (STG * 4u);                          \
        const float* a0p = ag + (kt) * 16 + g0 * 4;                           \
        const float* b0p = bg + (kt) * 16 + g0 * 4;                           \
        asm volatile("cp.async.cg.shared.global [%0], [%1], 16;"              \
                     :: "r"(aBase + off + sw0), "l"(a0p) : "memory");         \
        asm volatile("cp.async.cg.shared.global [%0], [%1], 16;"              \
                     :: "r"(aBase + off + sw1), "l"(a0p + 4) : "memory");     \
        asm volatile("cp.async.cg.shared.global [%0], [%1], 16;"              \
                     :: "r"(bBase + off + sw0), "l"(b0p) : "memory");         \
        asm volatile("cp.async.cg.shared.global [%0], [%1], 16;"              \
                     :: "r"(bBase + off + sw1), "l"(b0p + 4) : "memory");     \
        asm volatile("cp.async.commit_group;" ::: "memory");                  \
    } while (0)

    LOAD_STAGE(0, 0);
    LOAD_STAGE(1, 1);

    int cur = 0;
    int lb  = 2;

    for (int kt = 0; kt < NK; kt++) {
        if (kt + 1 < NK) {
            asm volatile("cp.async.wait_group 1;" ::: "memory");
        } else {
            asm volatile("cp.async.wait_group 0;" ::: "memory");
        }
        __syncthreads();

        if (kt + 2 < NK) LOAD_STAGE(lb, kt + 2);

        const float* Ab = As + cur * STG;
        const float* Bb = Bs + cur * STG;

        float aL4[2][4], aH4[2][4];
        #pragma unroll
        for (int mt = 0; mt < 2; mt++) {
            int rl = wm * 32 + mt * 16 + r;
            *(float4*)aL4[mt] =
                *(const float4*)&Ab[rl * 16 + ((c ^ (rl & 3)) * 4)];
            int rh = rl + 8;
            *(float4*)aH4[mt] =
                *(const float4*)&Ab[rh * 16 + ((c ^ (rh & 3)) * 4)];
        }

        #pragma unroll
        for (int nt = 0; nt < 8; nt++) {
            int nr = wn * 64 + nt * 8 + r;
            float bb4[4];
            *(float4*)bb4 =
                *(const float4*)&Bb[nr * 16 + ((c ^ (nr & 3)) * 4)];
            #pragma unroll
            for (int mt = 0; mt < 2; mt++) {
                mma_tf32(acc[mt][nt],
                         aL4[mt][0], aH4[mt][0], aL4[mt][1], aH4[mt][1],
                         bb4[0], bb4[1]);
                mma_tf32(acc[mt][nt],
                         aL4[mt][2], aH4[mt][2], aL4[mt][3], aH4[mt][3],
                         bb4[2], bb4[3]);
            }
        }

        cur = (cur == 2) ? 0 : cur + 1;
        lb  = (lb  == 2) ? 0 : lb  + 1;
    }
    #undef LOAD_STAGE

    #pragma unroll
    for (int mt = 0; mt < 2; mt++) {
        #pragma unroll
        for (int nt = 0; nt < 8; nt++) {
            int row = bm + wm * 32 + mt * 16 + r;
            int col = bn + wn * 64 + nt * 8 + 2 * c;
            *(float2*)&C[(size_t)row * NT_N + col] =
                make_float2(acc[mt][nt][0], acc[mt][nt][1]);
            *(float2*)&C[(size_t)(row + 8) * NT_N + col] =
                make_float2(acc[mt][nt][2], acc[mt][nt][3]);
        }
    }
}

// ---------------------------------------------------------------------------
// Tensor-core flash attention v3b: fragment-resident softmax.
// FIX vs R15: no cp.async vstage (cross-thread visibility race). V is loaded
// DIRECTLY from global in the transpose (coalesced 256B rows), fused with
// tf32 round, same as the k path. One __syncthreads per chunk; ks/vsT
// double-buffered so post-barrier PV readers never collide with the next
// chunk's pre-barrier writers.
// ---------------------------------------------------------------------------
struct AttnSmem {
    union {
        struct {
            float ks0[2][32][36];   // 9216 B
            float ks1[2][32][36];   // 9216 B
            float vsT[2][64][36];   // 18432 B
        } kv;
        float qstage[64][68];       // 17408 B (phase 0 only)
    } u;                             // 36864 B
};

__global__ void __launch_bounds__(256, 2) attn_kernel() {
    __shared__ AttnSmem sm;

    const int wi   = blockIdx.x;
    const int bh   = blockIdx.y;
    const int b    = bh >> 3;
    const int h    = bh & 7;
    const int tid  = threadIdx.x;
    const int warp = tid >> 5;
    const int lane = tid & 31;
    const int r    = lane >> 2;
    const int c    = lane & 3;
    const int row0 = warp * 16;
    const int rowA = row0 + r;
    const int rowB = row0 + r + 8;

    const float* __restrict__ qkv = g_qkv;

    // ---------------- phase 0: q fragments (rotated, tf32) ----------------
    float qa[8][4];
    #pragma unroll
    for (int half = 0; half < 2; half++) {
        {
            int sr = tid >> 2, quad = tid & 3;
            const float* qg = qkv +
                (size_t)(b * SEQ + wi * WS + half * 64 + sr) * DIM + h * DH;
            #pragma unroll
            for (int p = 0; p < 4; p++)
                *(float4*)&sm.u.qstage[sr][p * 16 + quad * 4] =
                    *(const float4*)(qg + p * 16 + quad * 4);
        }
        __syncthreads();
        #pragma unroll
        for (int p = 0; p < 8; p++) {
            int idx = p * 256 + tid;
            int sr = idx >> 5, e = idx & 31;
            int gi = (half * 64 + sr) * DH;
            float x1 = sm.u.qstage[sr][e], x2 = sm.u.qstage[sr][e + 32];
            float c1 = g_qcs[gi + e],      s1 = g_qsn[gi + e];
            float c2 = g_qcs[gi + e + 32], s2 = g_qsn[gi + e + 32];
            sm.u.qstage[sr][e]      = f2tf32(x1 * c1 - x2 * s1);
            sm.u.qstage[sr][e + 32] = f2tf32(x2 * c2 + x1 * s2);
        }
        __syncthreads();
        if ((warp >> 2) == half) {
            int lr = (warp & 3) * 16 + r;
            #pragma unroll
            for (int kk = 0; kk < 8; kk++) {
                qa[kk][0] = sm.u.qstage[lr][kk * 8 + c];
                qa[kk][1] = sm.u.qstage[lr + 8][kk * 8 + c];
                qa[kk][2] = sm.u.qstage[lr][kk * 8 + c + 4];
                qa[kk][3] = sm.u.qstage[lr + 8][kk * 8 + c + 4];
            }
        }
        __syncthreads();
    }

    float Oacc[8][4];
    #pragma unroll
    for (int nt = 0; nt < 8; nt++)
        #pragma unroll
        for (int q = 0; q < 4; q++) Oacc[nt][q] = 0.0f;

    float mA = NEG_INF, lA = 0.0f;
    float mB = NEG_INF, lB = 0.0f;

    const int chs = (wi == 0) ? 4 : 0;
    const int che = (wi == NWIN - 1) ? 8 : 12;

    for (int ch = chs; ch < che; ch++) {
        const int buf = ch & 1;

        // ---- phase A: v transpose (direct global) + k rotate into buf ----
        #pragma unroll
        for (int p = 0; p < 8; p++) {
            int idx = p * 256 + tid;
            int j = idx >> 6, e = idx & 63;
            const float* vg = qkv +
                (size_t)(b * SEQ + (wi - 1) * WS + ch * 32 + j) * DIM
                + INNER + h * DH;
            sm.u.kv.vsT[buf][e][PERM(j)] = f2tf32(vg[e]);
        }
        #pragma unroll
        for (int p = 0; p < 4; p++) {
            int j = (tid >> 5) + p * 8;
            int e = tid & 31;
            const float* kg = qkv +
                (size_t)(b * SEQ + (wi - 1) * WS + ch * 32 + j) * DIM + h * DH;
            float x1 = kg[e], x2 = kg[e + 32];
            int gi = (ch * 32 + j) * DH;
            sm.u.kv.ks0[buf][j][PERM(e)] =
                f2tf32(x1 * g_kcos[gi + e] - x2 * g_ksin[gi + e]);
            sm.u.kv.ks1[buf][j][PERM(e)] =
                f2tf32(x2 * g_kcos[gi + e + 32] + x1 * g_ksin[gi + e + 32]);
        }
        __syncthreads();   // the ONE barrier per chunk

        // ---- warp-level band skip ----
        if (32 * ch + 31 < row0 || 32 * ch > row0 + 271) continue;

        // ---- QK: S = Q.K^T (this warp's 16 rows x 32 j) ----
        float Sacc[4][4];
        #pragma unroll
        for (int nt = 0; nt < 4; nt++)
            #pragma unroll
            for (int q = 0; q < 4; q++) Sacc[nt][q] = 0.0f;
        #pragma unroll
        for (int nt = 0; nt < 4; nt++) {
            float bbA[2][4], bbB[2][4];
            int nr = nt * 8 + r;
            *(float4*)bbA[0] = *(const float4*)&sm.u.kv.ks0[buf][nr][c * 8];
            *(float4*)bbA[1] = *(const float4*)&sm.u.kv.ks0[buf][nr][c * 8 + 4];
            *(float4*)bbB[0] = *(const float4*)&sm.u.kv.ks1[buf][nr][c * 8];
            *(float4*)bbB[1] = *(const float4*)&sm.u.kv.ks1[buf][nr][c * 8 + 4];
            #pragma unroll
            for (int s = 0; s < 4; s++) {
                int q = s >> 1, o = (s & 1) * 2;
                mma_tf32(Sacc[nt], qa[s][0], qa[s][1], qa[s][2], qa[s][3],
                         bbA[q][o], bbA[q][o + 1]);
            }
            #pragma unroll
            for (int s = 0; s < 4; s++) {
                int q = s >> 1, o = (s & 1) * 2;
                mma_tf32(Sacc[nt], qa[4 + s][0], qa[4 + s][1],
                         qa[4 + s][2], qa[4 + s][3],
                         bbB[q][o], bbB[q][o + 1]);
            }
        }

        // ---- fragment softmax ----
        int jloA = rowA - 32 * ch, jhiA = jloA + 256;
        int jloB = rowB - 32 * ch, jhiB = jloB + 256;
        float sA[4][2], sB[4][2];
        float mcA = NEG_INF, mcB = NEG_INF;
        #pragma unroll
        for (int nt = 0; nt < 4; nt++) {
            #pragma unroll
            for (int e = 0; e < 2; e++) {
                int j = nt * 8 + 2 * c + e;
                sA[nt][e] = (j >= jloA && j <= jhiA) ? Sacc[nt][e] : NEG_INF;
                sB[nt][e] = (j >= jloB && j <= jhiB) ? Sacc[nt][2 + e] : NEG_INF;
                mcA = fmaxf(mcA, sA[nt][e]);
                mcB = fmaxf(mcB, sB[nt][e]);
            }
        }
        mcA = fmaxf(mcA, __shfl_xor_sync(0xffffffffu, mcA, 1));
        mcA = fmaxf(mcA, __shfl_xor_sync(0xffffffffu, mcA, 2));
        mcB = fmaxf(mcB, __shfl_xor_sync(0xffffffffu, mcB, 1));
        mcB = fmaxf(mcB, __shfl_xor_sync(0xffffffffu, mcB, 2));

        float mnA = fmaxf(mA, mcA);
        float mnB = fmaxf(mB, mcB);
        float crA = (mnA == NEG_INF) ? 1.0f : __expf(mA - mnA);
        float crB = (mnB == NEG_INF) ? 1.0f : __expf(mB - mnB);

        float pA[4][2], pB[4][2];
        float sumA = 0.0f, sumB = 0.0f;
        #pragma unroll
        for (int nt = 0; nt < 4; nt++) {
            #pragma unroll
            for (int e = 0; e < 2; e++) {
                float vA = (sA[nt][e] == NEG_INF) ? 0.0f
                           : __expf(sA[nt][e] - mnA);
                float vB = (sB[nt][e] == NEG_INF) ? 0.0f
                           : __expf(sB[nt][e] - mnB);
                sumA += vA; sumB += vB;
                pA[nt][e] = f2tf32(vA);
                pB[nt][e] = f2tf32(vB);
            }
        }
        sumA += __shfl_xor_sync(0xffffffffu, sumA, 1);
        sumA += __shfl_xor_sync(0xffffffffu, sumA, 2);
        sumB += __shfl_xor_sync(0xffffffffu, sumB, 1);
        sumB += __shfl_xor_sync(0xffffffffu, sumB, 2);
        lA = lA * crA + sumA;  mA = mnA;
        lB = lB * crB + sumB;  mB = mnB;

        // rescale O
        #pragma unroll
        for (int nt = 0; nt < 8; nt++) {
            Oacc[nt][0] *= crA; Oacc[nt][1] *= crA;
            Oacc[nt][2] *= crB; Oacc[nt][3] *= crB;
        }

        // ---- shuffle P into PV A-fragment: paX[m] = P[row][4m+c] ----
        float paA[8], paB[8];
        #pragma unroll
        for (int m = 0; m < 8; m++) {
            int src = (lane & ~3) | ((c >> 1) + 2 * (m & 1));
            float t0 = __shfl_sync(0xffffffffu, pA[m >> 1][0], src);
            float t1 = __shfl_sync(0xffffffffu, pA[m >> 1][1], src);
            paA[m] = (c & 1) ? t1 : t0;
            t0 = __shfl_sync(0xffffffffu, pB[m >> 1][0], src);
            t1 = __shfl_sync(0xffffffffu, pB[m >> 1][1], src);
            paB[m] = (c & 1) ? t1 : t0;
        }

        // ---- PV: O += P.V ----
        #pragma unroll
        for (int nt = 0; nt < 8; nt++) {
            float bb[2][4];
            int nr = nt * 8 + r;
            *(float4*)bb[0] = *(const float4*)&sm.u.kv.vsT[buf][nr][c * 8];
            *(float4*)bb[1] = *(const float4*)&sm.u.kv.vsT[buf][nr][c * 8 + 4];
            #pragma unroll
            for (int s = 0; s < 4; s++) {
                int q = s >> 1, o = (s & 1) * 2;
                mma_tf32(Oacc[nt], paA[4 * q + o], paB[4 * q + o],
                         paA[4 * q + o + 1], paB[4 * q + o + 1],
                         bb[q][o], bb[q][o + 1]);
            }
        }
    }

    // ---------------- finalize: write g_attn tf32-rounded + perm16 --------
    float invA = 1.0f / lA;
    float invB = 1.0f / lB;
    float* ob = g_attn + (size_t)(b * SEQ + wi * WS) * INNER + h * DH;
    #pragma unroll
    for (int nt = 0; nt < 8; nt++) {
        #pragma unroll
        for (int e = 0; e < 2; e++) {
            int col = nt * 8 + 2 * c + e;
            int slot = GSLOT16(col);
            ob[(size_t)rowA * INNER + slot] = f2tf32(Oacc[nt][e] * invA);
            ob[(size_t)rowB * INNER + slot] = f2tf32(Oacc[nt][2 + e] * invB);
        }
    }
}

// ---------------------------------------------------------------------------
// Launch: pure kernel launches, zero runtime API calls.
// ---------------------------------------------------------------------------
extern "C" void kernel_launch(void* const* d_in, const int* in_sizes, int n_in,
                              void* d_out, int out_size) {
    const float* x     = (const float*)d_in[0];
    const float* ln_g  = (const float*)d_in[1];
    const float* ln_b  = (const float*)d_in[2];
    const float* w_qkv = (const float*)d_in[3];
    const float* w_out = (const float*)d_in[4];
    float* out = (float*)d_out;

    rope_precompute_kernel<<<(JLEN * DH + 255) / 256, 256>>>();
    wperm_kernel<<<(DIM * DIM + 255) / 256, 256>>>(w_qkv, w_out);
    ln_kernel<<<M_ROWS, 256>>>(x, ln_g, ln_b);

    // qkv = xn @ w_qkv^T  (K=1024)
    gemm_mma<<<dim3(NT_N / 128, M_ROWS / 128), 256>>>(nullptr, DIM, 0);

    attn_kernel<<<dim3(NWIN, BATCH * HEADS), 256>>>();

    // out = attn @ w_out^T (K=512)
    gemm_mma<<<dim3(NT_N / 128, M_ROWS / 128), 256>>>(out, INNER, 1);
}